// round 6
// baseline (speedup 1.0000x reference)
#include <cuda_runtime.h>
#include <cuda_fp16.h>
#include <cstdint>

#define HH   768
#define WW   768
#define HID  256
#define NPIX (HH*WW)

// ---------------- scratch ----------------
__device__ float    g_hx[HH * HID];
__device__ float    g_hy[WW * HID];
__device__ uint32_t g_hxh[HH * HID / 2];   // half2-packed
__device__ uint32_t g_hyh[WW * HID / 2];
__device__ float    g_part[2][3 * NPIX];

// ---------------- helpers ----------------
__device__ __forceinline__ uint32_t pack_h2(float lo, float hi) {
    __half2 h = __floats2half2_rn(lo, hi);
    return *reinterpret_cast<uint32_t*>(&h);
}
__device__ __forceinline__ uint32_t hmul2u(uint32_t a, uint32_t b) {
    uint32_t d;
    asm("mul.f16x2 %0, %1, %2;" : "=r"(d) : "r"(a), "r"(b));
    return d;
}
__device__ __forceinline__ float fast_sin(float x) {
    const float INV_PI = 0.3183098861837907f;
    const float PI_HI  = 3.14159274101257324f;
    const float PI_LO  = -8.742277657347586e-8f;
    int   iq = __float2int_rn(x * INV_PI);
    float fq = (float)iq;
    float r  = fmaf(fq, -PI_HI, x);
    r        = fmaf(fq, -PI_LO, r);
    float r2 = r * r;
    float p  = fmaf(r2, 2.7183114939898219e-6f, -1.9839334836096632e-4f);
    p        = fmaf(r2, p, 8.3333293858894632e-3f);
    p        = fmaf(r2, p, -1.6666666641626524e-1f);
    p        = fmaf(r2 * r, p, r);
    return (iq & 1) ? -p : p;
}

#define MMA_F16(d, a, b0, b1) \
    asm volatile("mma.sync.aligned.m16n8k16.row.col.f32.f16.f16.f32 " \
        "{%0,%1,%2,%3}, {%4,%5,%6,%7}, {%8,%9}, {%0,%1,%2,%3};" \
        : "+f"((d)[0]), "+f"((d)[1]), "+f"((d)[2]), "+f"((d)[3]) \
        : "r"((a)[0]), "r"((a)[1]), "r"((a)[2]), "r"((a)[3]), \
          "r"(b0), "r"(b1))

// ---------------------------------------------------------------------------
// branch networks: 1024 threads/block, k-split partials + smem combine.
// ---------------------------------------------------------------------------
#define BR_SMEM_FLOATS (4096 + 4096 + 16384)   // s0, s1, sp
__global__ __launch_bounds__(1024)
void branch_kernel(const float* __restrict__ x, const float* __restrict__ y,
                   const float* __restrict__ Wbx, const float* __restrict__ bbx,
                   const float* __restrict__ Wby, const float* __restrict__ bby,
                   const float* __restrict__ Wp1, const float* __restrict__ bp1,
                   const float* __restrict__ Wp2, const float* __restrict__ bp2)
{
    extern __shared__ float sm[];
    float* s0 = sm;            // [16][256]
    float* s1 = sm + 4096;     // [16][256]
    float* sp = sm + 8192;     // partials: h1 view [4][16][256], h2 view [2][16][512]

    const int tid = threadIdx.x;
    const int t   = tid & 255;
    const int q   = tid >> 8;           // k-quarter 0..3
    const int br  = blockIdx.y;
    const float* coord = br ? y   : x;
    const float* Wb    = br ? Wby : Wbx;
    const float* bb    = br ? bby : bbx;
    float*       outp  = br ? g_hy : g_hx;
    const int r0 = blockIdx.x * 16;

    if (q == 0) {
        float wv = Wb[t], bv = bb[t];
        #pragma unroll
        for (int r = 0; r < 16; r++)
            s0[r * 256 + t] = fast_sin(fmaf(coord[r0 + r], wv, bv));
    }
    __syncthreads();

    // h1 partial over k in [64q, 64q+64)
    {
        float acc[16];
        #pragma unroll
        for (int r = 0; r < 16; r++) acc[r] = 0.0f;
        const float4* wrow = (const float4*)(Wp1 + (size_t)t * HID + 64 * q);
        #pragma unroll 4
        for (int k4 = 0; k4 < 16; k4++) {
            float4 w = wrow[k4];
            const int base = 64 * q + 4 * k4;
            #pragma unroll
            for (int r = 0; r < 16; r++) {
                float4 h = *(const float4*)&s0[r * 256 + base];
                acc[r] = fmaf(w.x, h.x, acc[r]); acc[r] = fmaf(w.y, h.y, acc[r]);
                acc[r] = fmaf(w.z, h.z, acc[r]); acc[r] = fmaf(w.w, h.w, acc[r]);
            }
        }
        #pragma unroll
        for (int r = 0; r < 16; r++) sp[(q * 16 + r) * 256 + t] = acc[r];
    }
    __syncthreads();
    if (q == 0) {
        float b = bp1[t];
        #pragma unroll
        for (int r = 0; r < 16; r++) {
            float v = b + sp[r * 256 + t] + sp[(16 + r) * 256 + t]
                        + sp[(32 + r) * 256 + t] + sp[(48 + r) * 256 + t];
            s1[r * 256 + t] = fast_sin(v);
        }
    }
    __syncthreads();

    // h2 partial: output n = tid&511 over k in [128kh, 128kh+128)
    {
        const int n  = tid & 511;
        const int kh = tid >> 9;
        float acc[16];
        #pragma unroll
        for (int r = 0; r < 16; r++) acc[r] = 0.0f;
        const float4* wrow = (const float4*)(Wp2 + (size_t)n * HID + 128 * kh);
        #pragma unroll 4
        for (int k4 = 0; k4 < 32; k4++) {
            float4 w = wrow[k4];
            const int base = 128 * kh + 4 * k4;
            #pragma unroll
            for (int r = 0; r < 16; r++) {
                float4 h = *(const float4*)&s1[r * 256 + base];
                acc[r] = fmaf(w.x, h.x, acc[r]); acc[r] = fmaf(w.y, h.y, acc[r]);
                acc[r] = fmaf(w.z, h.z, acc[r]); acc[r] = fmaf(w.w, h.w, acc[r]);
            }
        }
        __syncthreads();   // sp reuse: all h1 reads complete
        #pragma unroll
        for (int r = 0; r < 16; r++) sp[(kh * 16 + r) * 512 + n] = acc[r];
    }
    __syncthreads();
    if (tid < 256) {
        float b0 = bp2[t], b1 = bp2[t + 256];
        #pragma unroll
        for (int r = 0; r < 16; r++) {
            float v0 = b0 + sp[r * 512 + t]       + sp[(16 + r) * 512 + t];
            float v1 = b1 + sp[r * 512 + t + 256] + sp[(16 + r) * 512 + t + 256];
            outp[(size_t)(r0 + r) * HID + t] = fast_sin(v0) + fast_sin(v1);
        }
    }
}

// ---------------------------------------------------------------------------
// pack hx/hy to half2
// ---------------------------------------------------------------------------
__global__ __launch_bounds__(256)
void pack_kernel()
{
    const int half_n = HH * HID / 2;   // 98304
    int id = blockIdx.x * 256 + threadIdx.x;
    if (id < 2 * half_n) {
        const float2* src = (id < half_n) ? (const float2*)g_hx : (const float2*)g_hy;
        uint32_t*     dst = (id < half_n) ? g_hxh : g_hyh;
        int k = (id < half_n) ? id : id - half_n;
        float2 v = src[k];
        dst[k] = pack_h2(v.x, v.y);
    }
}

// ---------------------------------------------------------------------------
// merge: persistent fp16 mma.sync m16n8k16.
// CTA tile M=256 (32i x 8j) x N=128 (half) x K=256. Warp owns one j, full N.
// ---------------------------------------------------------------------------
#define SMB_B    0         // 16384 u32 fp16 fragments = 65536 B
#define SMB_HX   65536     // 32 rows x 132 u32 = 16896 B
#define SMB_HY   82432     // 8 rows x 132 u32 = 4224 B
#define SMB_BM1  86656     // 128 f32
#define SMB_WM2  87168     // 3 x 128 f32
#define SMB_TOT  88704

#define HXP 132            // u32 (half2) pitch: bank = 4*row + qk, conflict-free
#define N_ITILES 24
#define TILES    (N_ITILES * 96)   // 2304 per half
#define N_GROUPS 74

__global__ __launch_bounds__(256, 1)
void merge_kernel(const float* __restrict__ Wm1, const float* __restrict__ bm1,
                  const float* __restrict__ Wm2)
{
    extern __shared__ __align__(16) char smem[];
    uint32_t* sBh   = (uint32_t*)(smem + SMB_B);
    uint32_t* s_hx2 = (uint32_t*)(smem + SMB_HX);
    uint32_t* s_hy2 = (uint32_t*)(smem + SMB_HY);
    float*    s_b1  = (float*)(smem + SMB_BM1);
    float*    s_w2  = (float*)(smem + SMB_WM2);

    const int tid  = threadIdx.x;
    const int wid  = tid >> 5;
    const int lane = tid & 31;
    const int qk   = lane & 3;
    const int qr   = lane >> 2;

    const int cta   = blockIdx.x;
    const int hlf   = cta & 1;
    const int group = cta >> 1;
    const int h0    = hlf * 128;

    // ---- one-time: B-half as fp16 mma fragments ----
    // (n,p): p = k-pair. kt=p>>3, reg=(p&7)>>2, qk_l=p&3, nt=n>>3, qr_l=n&7,
    // pr=nt>>1, sub=nt&1. slot = ((kt*8+pr)*32 + qr_l*4+qk_l)*4 + sub*2 + reg
    for (int idx = tid; idx < 128 * 64; idx += 256) {
        const int n  = idx >> 6;
        const int f4 = idx & 63;
        float4 v = *(const float4*)(Wm1 + (size_t)(h0 + n) * HID + f4 * 4);
        uint32_t h2a = pack_h2(v.x, v.y);   // pair p0 = 2*f4
        uint32_t h2b = pack_h2(v.z, v.w);   // pair p1 = 2*f4+1
        const int nt = n >> 3, qr_l = n & 7, pr = nt >> 1, sub = nt & 1;
        #pragma unroll
        for (int e = 0; e < 2; e++) {
            const int p  = 2 * f4 + e;
            const int kt = p >> 3, w8 = p & 7;
            const int slot = (((kt * 8 + pr) * 32 + qr_l * 4 + (w8 & 3)) * 4)
                             + sub * 2 + (w8 >> 2);
            sBh[slot] = e ? h2b : h2a;
        }
    }
    if (tid < 128) s_b1[tid] = bm1[h0 + tid];
    for (int idx = tid; idx < 384; idx += 256) {
        const int c = idx >> 7, n = idx & 127;
        s_w2[c * 128 + n] = Wm2[c * HID + h0 + n];
    }
    __syncthreads();

    // ---- persistent tile loop ----
    for (int t = group; t < TILES; t += N_GROUPS) {
        const int i0 = (t % N_ITILES) * 32;
        const int j0 = (t / N_ITILES) * 8;

        __syncthreads();
        // stage hx (32 rows x 128 half2) / hy (8 x 128) via uint4
        for (int idx = tid; idx < 1024; idx += 256) {
            const int r = idx >> 5, c = idx & 31;
            *(uint4*)(s_hx2 + r * HXP + c * 4) =
                ((const uint4*)(g_hxh + (size_t)(i0 + r) * 128))[c];
        }
        {
            const int r = tid >> 5, c = tid & 31;
            *(uint4*)(s_hy2 + r * HXP + c * 4) =
                ((const uint4*)(g_hyh + (size_t)(j0 + r) * 128))[c];
        }
        __syncthreads();

        // accumulators initialized with bm1 (MMA accumulates on top)
        float d[2][16][4];
        #pragma unroll
        for (int nt = 0; nt < 16; nt++) {
            const float b0 = s_b1[nt * 8 + qk * 2 + 0];
            const float b1 = s_b1[nt * 8 + qk * 2 + 1];
            #pragma unroll
            for (int ih = 0; ih < 2; ih++) {
                d[ih][nt][0] = b0; d[ih][nt][1] = b1;
                d[ih][nt][2] = b0; d[ih][nt][3] = b1;
            }
        }

        const uint32_t* hxb = s_hx2 + qr * HXP;
        const int jbase = wid * HXP;

        #pragma unroll 2
        for (int kt = 0; kt < 16; kt++) {
            const uint32_t hyl = s_hy2[jbase + 8 * kt + qk];
            const uint32_t hyh = s_hy2[jbase + 8 * kt + qk + 4];
            uint32_t xl[4], xh[4];
            #pragma unroll
            for (int u = 0; u < 4; u++) {
                xl[u] = hxb[u * 8 * HXP + 8 * kt + qk];
                xh[u] = hxb[u * 8 * HXP + 8 * kt + qk + 4];
            }
            uint32_t a[2][4];
            #pragma unroll
            for (int ih = 0; ih < 2; ih++) {
                a[ih][0] = hmul2u(xl[2 * ih + 0], hyl);
                a[ih][1] = hmul2u(xl[2 * ih + 1], hyl);
                a[ih][2] = hmul2u(xh[2 * ih + 0], hyh);
                a[ih][3] = hmul2u(xh[2 * ih + 1], hyh);
            }
            const uint4* bp4 = (const uint4*)sBh + (size_t)(kt * 8) * 32 + lane;
            #pragma unroll
            for (int p = 0; p < 8; p++) {
                uint4 B2 = bp4[p * 32];
                MMA_F16(d[0][2 * p],     a[0], B2.x, B2.y);
                MMA_F16(d[1][2 * p],     a[1], B2.x, B2.y);
                MMA_F16(d[0][2 * p + 1], a[0], B2.z, B2.w);
                MMA_F16(d[1][2 * p + 1], a[1], B2.z, B2.w);
            }
        }

        // ---- epilogue: sin + Wm2 fold + quad reduce + single-owner store ----
        const int j = j0 + wid;
        #pragma unroll
        for (int ih = 0; ih < 2; ih++) {
            #pragma unroll
            for (int h = 0; h < 2; h++) {
                const int i = i0 + ih * 16 + qr + 8 * h;
                float p0 = 0.f, p1 = 0.f, p2 = 0.f;
                #pragma unroll
                for (int nt = 0; nt < 16; nt++) {
                    #pragma unroll
                    for (int c = 0; c < 2; c++) {
                        const int nl = nt * 8 + qk * 2 + c;
                        float hv = __sinf(d[ih][nt][2 * h + c]);
                        p0 = fmaf(s_w2[nl],       hv, p0);
                        p1 = fmaf(s_w2[128 + nl], hv, p1);
                        p2 = fmaf(s_w2[256 + nl], hv, p2);
                    }
                }
                p0 += __shfl_xor_sync(0xffffffffu, p0, 1);
                p0 += __shfl_xor_sync(0xffffffffu, p0, 2);
                p1 += __shfl_xor_sync(0xffffffffu, p1, 1);
                p1 += __shfl_xor_sync(0xffffffffu, p1, 2);
                p2 += __shfl_xor_sync(0xffffffffu, p2, 1);
                p2 += __shfl_xor_sync(0xffffffffu, p2, 2);
                if (qk == 0) {
                    float* dst = &g_part[hlf][(size_t)j * HH + i];
                    dst[0]        = p0;
                    dst[NPIX]     = p1;
                    dst[2 * NPIX] = p2;
                }
            }
        }
    }
}

// ---------------------------------------------------------------------------
__global__ __launch_bounds__(256)
void final_kernel(const float* __restrict__ bm2, float* __restrict__ out)
{
    const int idx = blockIdx.x * 256 + threadIdx.x;
    if (idx < 3 * NPIX) {
        const int c = idx / NPIX;
        float v = g_part[0][idx] + g_part[1][idx] + bm2[c];
        out[idx] = __fdividef(1.0f, 1.0f + __expf(-v));
    }
}

// ---------------------------------------------------------------------------
extern "C" void kernel_launch(void* const* d_in, const int* in_sizes, int n_in,
                              void* d_out, int out_size) {
    const float* x   = (const float*)d_in[0];
    const float* y   = (const float*)d_in[1];
    const float* Wbx = (const float*)d_in[2];
    const float* bbx = (const float*)d_in[3];
    const float* Wby = (const float*)d_in[4];
    const float* bby = (const float*)d_in[5];
    const float* Wp1 = (const float*)d_in[6];
    const float* bp1 = (const float*)d_in[7];
    const float* Wp2 = (const float*)d_in[8];
    const float* bp2 = (const float*)d_in[9];
    const float* Wm1 = (const float*)d_in[10];
    const float* bm1 = (const float*)d_in[11];
    const float* Wm2 = (const float*)d_in[12];
    const float* bm2 = (const float*)d_in[13];
    float* out = (float*)d_out;

    cudaFuncSetAttribute(branch_kernel,
                         cudaFuncAttributeMaxDynamicSharedMemorySize,
                         BR_SMEM_FLOATS * 4);
    cudaFuncSetAttribute(merge_kernel,
                         cudaFuncAttributeMaxDynamicSharedMemorySize, SMB_TOT);

    branch_kernel<<<dim3(HH / 16, 2), 1024, BR_SMEM_FLOATS * 4>>>(
        x, y, Wbx, bbx, Wby, bby, Wp1, bp1, Wp2, bp2);
    pack_kernel<<<768, 256>>>();
    merge_kernel<<<148, 256, SMB_TOT>>>(Wm1, bm1, Wm2);
    final_kernel<<<(3 * NPIX + 255) / 256, 256>>>(bm2, out);
}

// round 7
// speedup vs baseline: 1.0025x; 1.0025x over previous
#include <cuda_runtime.h>
#include <cuda_fp16.h>
#include <cstdint>

#define HH   768
#define WW   768
#define HID  256
#define NPIX (HH*WW)

// ---------------- scratch ----------------
__device__ float    g_hx[HH * HID];
__device__ float    g_hy[WW * HID];
__device__ uint32_t g_hxh[HH * HID / 2];   // half2-packed
__device__ uint32_t g_hyh[WW * HID / 2];
__device__ float    g_part[2][3 * NPIX];

// ---------------- helpers ----------------
__device__ __forceinline__ uint32_t pack_h2(float lo, float hi) {
    __half2 h = __floats2half2_rn(lo, hi);
    return *reinterpret_cast<uint32_t*>(&h);
}
__device__ __forceinline__ uint32_t hmul2u(uint32_t a, uint32_t b) {
    uint32_t d;
    asm("mul.f16x2 %0, %1, %2;" : "=r"(d) : "r"(a), "r"(b));
    return d;
}
__device__ __forceinline__ float fast_sin(float x) {
    const float INV_PI = 0.3183098861837907f;
    const float PI_HI  = 3.14159274101257324f;
    const float PI_LO  = -8.742277657347586e-8f;
    int   iq = __float2int_rn(x * INV_PI);
    float fq = (float)iq;
    float r  = fmaf(fq, -PI_HI, x);
    r        = fmaf(fq, -PI_LO, r);
    float r2 = r * r;
    float p  = fmaf(r2, 2.7183114939898219e-6f, -1.9839334836096632e-4f);
    p        = fmaf(r2, p, 8.3333293858894632e-3f);
    p        = fmaf(r2, p, -1.6666666641626524e-1f);
    p        = fmaf(r2 * r, p, r);
    return (iq & 1) ? -p : p;
}

#define MMA_F16(d, a, b0, b1) \
    asm volatile("mma.sync.aligned.m16n8k16.row.col.f32.f16.f16.f32 " \
        "{%0,%1,%2,%3}, {%4,%5,%6,%7}, {%8,%9}, {%0,%1,%2,%3};" \
        : "+f"((d)[0]), "+f"((d)[1]), "+f"((d)[2]), "+f"((d)[3]) \
        : "r"((a)[0]), "r"((a)[1]), "r"((a)[2]), "r"((a)[3]), \
          "r"(b0), "r"(b1))

// ---------------------------------------------------------------------------
// branch networks: 1024 threads/block, k-split partials + smem combine.
// ---------------------------------------------------------------------------
#define BR_SMEM_FLOATS (4096 + 4096 + 16384)   // s0, s1, sp
__global__ __launch_bounds__(1024)
void branch_kernel(const float* __restrict__ x, const float* __restrict__ y,
                   const float* __restrict__ Wbx, const float* __restrict__ bbx,
                   const float* __restrict__ Wby, const float* __restrict__ bby,
                   const float* __restrict__ Wp1, const float* __restrict__ bp1,
                   const float* __restrict__ Wp2, const float* __restrict__ bp2)
{
    extern __shared__ float sm[];
    float* s0 = sm;            // [16][256]
    float* s1 = sm + 4096;     // [16][256]
    float* sp = sm + 8192;     // partials: h1 view [4][16][256], h2 view [2][16][512]

    const int tid = threadIdx.x;
    const int t   = tid & 255;
    const int q   = tid >> 8;           // k-quarter 0..3
    const int br  = blockIdx.y;
    const float* coord = br ? y   : x;
    const float* Wb    = br ? Wby : Wbx;
    const float* bb    = br ? bby : bbx;
    float*       outp  = br ? g_hy : g_hx;
    const int r0 = blockIdx.x * 16;

    if (q == 0) {
        float wv = Wb[t], bv = bb[t];
        #pragma unroll
        for (int r = 0; r < 16; r++)
            s0[r * 256 + t] = fast_sin(fmaf(coord[r0 + r], wv, bv));
    }
    __syncthreads();

    // h1 partial over k in [64q, 64q+64)
    {
        float acc[16];
        #pragma unroll
        for (int r = 0; r < 16; r++) acc[r] = 0.0f;
        const float4* wrow = (const float4*)(Wp1 + (size_t)t * HID + 64 * q);
        #pragma unroll 4
        for (int k4 = 0; k4 < 16; k4++) {
            float4 w = wrow[k4];
            const int base = 64 * q + 4 * k4;
            #pragma unroll
            for (int r = 0; r < 16; r++) {
                float4 h = *(const float4*)&s0[r * 256 + base];
                acc[r] = fmaf(w.x, h.x, acc[r]); acc[r] = fmaf(w.y, h.y, acc[r]);
                acc[r] = fmaf(w.z, h.z, acc[r]); acc[r] = fmaf(w.w, h.w, acc[r]);
            }
        }
        #pragma unroll
        for (int r = 0; r < 16; r++) sp[(q * 16 + r) * 256 + t] = acc[r];
    }
    __syncthreads();
    if (q == 0) {
        float b = bp1[t];
        #pragma unroll
        for (int r = 0; r < 16; r++) {
            float v = b + sp[r * 256 + t] + sp[(16 + r) * 256 + t]
                        + sp[(32 + r) * 256 + t] + sp[(48 + r) * 256 + t];
            s1[r * 256 + t] = fast_sin(v);
        }
    }
    __syncthreads();

    // h2 partial: output n = tid&511 over k in [128kh, 128kh+128)
    {
        const int n  = tid & 511;
        const int kh = tid >> 9;
        float acc[16];
        #pragma unroll
        for (int r = 0; r < 16; r++) acc[r] = 0.0f;
        const float4* wrow = (const float4*)(Wp2 + (size_t)n * HID + 128 * kh);
        #pragma unroll 4
        for (int k4 = 0; k4 < 32; k4++) {
            float4 w = wrow[k4];
            const int base = 128 * kh + 4 * k4;
            #pragma unroll
            for (int r = 0; r < 16; r++) {
                float4 h = *(const float4*)&s1[r * 256 + base];
                acc[r] = fmaf(w.x, h.x, acc[r]); acc[r] = fmaf(w.y, h.y, acc[r]);
                acc[r] = fmaf(w.z, h.z, acc[r]); acc[r] = fmaf(w.w, h.w, acc[r]);
            }
        }
        __syncthreads();   // sp reuse: all h1 reads complete
        #pragma unroll
        for (int r = 0; r < 16; r++) sp[(kh * 16 + r) * 512 + n] = acc[r];
    }
    __syncthreads();
    if (tid < 256) {
        float b0 = bp2[t], b1 = bp2[t + 256];
        #pragma unroll
        for (int r = 0; r < 16; r++) {
            float v0 = b0 + sp[r * 512 + t]       + sp[(16 + r) * 512 + t];
            float v1 = b1 + sp[r * 512 + t + 256] + sp[(16 + r) * 512 + t + 256];
            outp[(size_t)(r0 + r) * HID + t] = fast_sin(v0) + fast_sin(v1);
        }
    }
}

// ---------------------------------------------------------------------------
// pack hx/hy to half2
// ---------------------------------------------------------------------------
__global__ __launch_bounds__(256)
void pack_kernel()
{
    const int half_n = HH * HID / 2;   // 98304
    int id = blockIdx.x * 256 + threadIdx.x;
    if (id < 2 * half_n) {
        const float2* src = (id < half_n) ? (const float2*)g_hx : (const float2*)g_hy;
        uint32_t*     dst = (id < half_n) ? g_hxh : g_hyh;
        int k = (id < half_n) ? id : id - half_n;
        float2 v = src[k];
        dst[k] = pack_h2(v.x, v.y);
    }
}

// ---------------------------------------------------------------------------
// merge: persistent fp16 mma.sync m16n8k16.
// CTA tile M=256 (32i x 8j) x N=128 (half) x K=256. Warp owns one j, full N.
// ---------------------------------------------------------------------------
#define SMB_B    0         // 16384 u32 fp16 fragments = 65536 B
#define SMB_HX   65536     // 32 rows x 132 u32 = 16896 B
#define SMB_HY   82432     // 8 rows x 132 u32 = 4224 B
#define SMB_BM1  86656     // 128 f32
#define SMB_WM2  87168     // 3 x 128 f32
#define SMB_TOT  88704

#define HXP 132            // u32 (half2) pitch: bank = 4*row + qk, conflict-free
#define N_ITILES 24
#define TILES    (N_ITILES * 96)   // 2304 per half
#define N_GROUPS 74

__global__ __launch_bounds__(256, 1)
void merge_kernel(const float* __restrict__ Wm1, const float* __restrict__ bm1,
                  const float* __restrict__ Wm2)
{
    extern __shared__ __align__(16) char smem[];
    uint32_t* sBh   = (uint32_t*)(smem + SMB_B);
    uint32_t* s_hx2 = (uint32_t*)(smem + SMB_HX);
    uint32_t* s_hy2 = (uint32_t*)(smem + SMB_HY);
    float*    s_b1  = (float*)(smem + SMB_BM1);
    float*    s_w2  = (float*)(smem + SMB_WM2);

    const int tid  = threadIdx.x;
    const int wid  = tid >> 5;
    const int lane = tid & 31;
    const int qk   = lane & 3;
    const int qr   = lane >> 2;

    const int cta   = blockIdx.x;
    const int hlf   = cta & 1;
    const int group = cta >> 1;
    const int h0    = hlf * 128;

    // ---- one-time: B-half as fp16 mma fragments ----
    // (n,p): p = k-pair. kt=p>>3, reg=(p&7)>>2, qk_l=p&3, nt=n>>3, qr_l=n&7,
    // pr=nt>>1, sub=nt&1. slot = ((kt*8+pr)*32 + qr_l*4+qk_l)*4 + sub*2 + reg
    for (int idx = tid; idx < 128 * 64; idx += 256) {
        const int n  = idx >> 6;
        const int f4 = idx & 63;
        float4 v = *(const float4*)(Wm1 + (size_t)(h0 + n) * HID + f4 * 4);
        uint32_t h2a = pack_h2(v.x, v.y);   // pair p0 = 2*f4
        uint32_t h2b = pack_h2(v.z, v.w);   // pair p1 = 2*f4+1
        const int nt = n >> 3, qr_l = n & 7, pr = nt >> 1, sub = nt & 1;
        #pragma unroll
        for (int e = 0; e < 2; e++) {
            const int p  = 2 * f4 + e;
            const int kt = p >> 3, w8 = p & 7;
            const int slot = (((kt * 8 + pr) * 32 + qr_l * 4 + (w8 & 3)) * 4)
                             + sub * 2 + (w8 >> 2);
            sBh[slot] = e ? h2b : h2a;
        }
    }
    if (tid < 128) s_b1[tid] = bm1[h0 + tid];
    for (int idx = tid; idx < 384; idx += 256) {
        const int c = idx >> 7, n = idx & 127;
        s_w2[c * 128 + n] = Wm2[c * HID + h0 + n];
    }
    __syncthreads();

    // ---- persistent tile loop ----
    for (int t = group; t < TILES; t += N_GROUPS) {
        const int i0 = (t % N_ITILES) * 32;
        const int j0 = (t / N_ITILES) * 8;

        __syncthreads();
        // stage hx (32 rows x 128 half2) / hy (8 x 128) via uint4
        for (int idx = tid; idx < 1024; idx += 256) {
            const int r = idx >> 5, c = idx & 31;
            *(uint4*)(s_hx2 + r * HXP + c * 4) =
                ((const uint4*)(g_hxh + (size_t)(i0 + r) * 128))[c];
        }
        {
            const int r = tid >> 5, c = tid & 31;
            *(uint4*)(s_hy2 + r * HXP + c * 4) =
                ((const uint4*)(g_hyh + (size_t)(j0 + r) * 128))[c];
        }
        __syncthreads();

        // accumulators initialized with bm1 (MMA accumulates on top)
        float d[2][16][4];
        #pragma unroll
        for (int nt = 0; nt < 16; nt++) {
            const float b0 = s_b1[nt * 8 + qk * 2 + 0];
            const float b1 = s_b1[nt * 8 + qk * 2 + 1];
            #pragma unroll
            for (int ih = 0; ih < 2; ih++) {
                d[ih][nt][0] = b0; d[ih][nt][1] = b1;
                d[ih][nt][2] = b0; d[ih][nt][3] = b1;
            }
        }

        const uint32_t* hxb = s_hx2 + qr * HXP;
        const int jbase = wid * HXP;

        #pragma unroll 2
        for (int kt = 0; kt < 16; kt++) {
            const uint32_t hyl = s_hy2[jbase + 8 * kt + qk];
            const uint32_t hyh = s_hy2[jbase + 8 * kt + qk + 4];
            uint32_t xl[4], xh[4];
            #pragma unroll
            for (int u = 0; u < 4; u++) {
                xl[u] = hxb[u * 8 * HXP + 8 * kt + qk];
                xh[u] = hxb[u * 8 * HXP + 8 * kt + qk + 4];
            }
            uint32_t a[2][4];
            #pragma unroll
            for (int ih = 0; ih < 2; ih++) {
                a[ih][0] = hmul2u(xl[2 * ih + 0], hyl);
                a[ih][1] = hmul2u(xl[2 * ih + 1], hyl);
                a[ih][2] = hmul2u(xh[2 * ih + 0], hyh);
                a[ih][3] = hmul2u(xh[2 * ih + 1], hyh);
            }
            const uint4* bp4 = (const uint4*)sBh + (size_t)(kt * 8) * 32 + lane;
            #pragma unroll
            for (int p = 0; p < 8; p++) {
                uint4 B2 = bp4[p * 32];
                MMA_F16(d[0][2 * p],     a[0], B2.x, B2.y);
                MMA_F16(d[1][2 * p],     a[1], B2.x, B2.y);
                MMA_F16(d[0][2 * p + 1], a[0], B2.z, B2.w);
                MMA_F16(d[1][2 * p + 1], a[1], B2.z, B2.w);
            }
        }

        // ---- epilogue: sin + Wm2 fold + quad reduce + single-owner store ----
        const int j = j0 + wid;
        #pragma unroll
        for (int ih = 0; ih < 2; ih++) {
            #pragma unroll
            for (int h = 0; h < 2; h++) {
                const int i = i0 + ih * 16 + qr + 8 * h;
                float p0 = 0.f, p1 = 0.f, p2 = 0.f;
                #pragma unroll
                for (int nt = 0; nt < 16; nt++) {
                    #pragma unroll
                    for (int c = 0; c < 2; c++) {
                        const int nl = nt * 8 + qk * 2 + c;
                        float hv = __sinf(d[ih][nt][2 * h + c]);
                        p0 = fmaf(s_w2[nl],       hv, p0);
                        p1 = fmaf(s_w2[128 + nl], hv, p1);
                        p2 = fmaf(s_w2[256 + nl], hv, p2);
                    }
                }
                p0 += __shfl_xor_sync(0xffffffffu, p0, 1);
                p0 += __shfl_xor_sync(0xffffffffu, p0, 2);
                p1 += __shfl_xor_sync(0xffffffffu, p1, 1);
                p1 += __shfl_xor_sync(0xffffffffu, p1, 2);
                p2 += __shfl_xor_sync(0xffffffffu, p2, 1);
                p2 += __shfl_xor_sync(0xffffffffu, p2, 2);
                if (qk == 0) {
                    float* dst = &g_part[hlf][(size_t)j * HH + i];
                    dst[0]        = p0;
                    dst[NPIX]     = p1;
                    dst[2 * NPIX] = p2;
                }
            }
        }
    }
}

// ---------------------------------------------------------------------------
__global__ __launch_bounds__(256)
void final_kernel(const float* __restrict__ bm2, float* __restrict__ out)
{
    const int idx = blockIdx.x * 256 + threadIdx.x;
    if (idx < 3 * NPIX) {
        const int c = idx / NPIX;
        float v = g_part[0][idx] + g_part[1][idx] + bm2[c];
        out[idx] = __fdividef(1.0f, 1.0f + __expf(-v));
    }
}

// ---------------------------------------------------------------------------
extern "C" void kernel_launch(void* const* d_in, const int* in_sizes, int n_in,
                              void* d_out, int out_size) {
    const float* x   = (const float*)d_in[0];
    const float* y   = (const float*)d_in[1];
    const float* Wbx = (const float*)d_in[2];
    const float* bbx = (const float*)d_in[3];
    const float* Wby = (const float*)d_in[4];
    const float* bby = (const float*)d_in[5];
    const float* Wp1 = (const float*)d_in[6];
    const float* bp1 = (const float*)d_in[7];
    const float* Wp2 = (const float*)d_in[8];
    const float* bp2 = (const float*)d_in[9];
    const float* Wm1 = (const float*)d_in[10];
    const float* bm1 = (const float*)d_in[11];
    const float* Wm2 = (const float*)d_in[12];
    const float* bm2 = (const float*)d_in[13];
    float* out = (float*)d_out;

    cudaFuncSetAttribute(branch_kernel,
                         cudaFuncAttributeMaxDynamicSharedMemorySize,
                         BR_SMEM_FLOATS * 4);
    cudaFuncSetAttribute(merge_kernel,
                         cudaFuncAttributeMaxDynamicSharedMemorySize, SMB_TOT);

    branch_kernel<<<dim3(HH / 16, 2), 1024, BR_SMEM_FLOATS * 4>>>(
        x, y, Wbx, bbx, Wby, bby, Wp1, bp1, Wp2, bp2);
    pack_kernel<<<768, 256>>>();
    merge_kernel<<<148, 256, SMB_TOT>>>(Wm1, bm1, Wm2);
    final_kernel<<<(3 * NPIX + 255) / 256, 256>>>(bm2, out);
}

// round 9
// speedup vs baseline: 1.0206x; 1.0180x over previous
#include <cuda_runtime.h>
#include <cuda_fp16.h>
#include <cstdint>

#define HH   768
#define WW   768
#define HID  256
#define NPIX (HH*WW)

// ---------------- scratch ----------------
// interleaved half2 layout per row: 64 uint2 slots; slot s=(kt*4+qk) holds
// half2 pairs { p = 8kt+qk, p+4 }  (p indexes n-pairs: n = 2p, 2p+1)
__device__ uint32_t g_hxh[HH * 128];
__device__ uint32_t g_hyh[WW * 128];
__device__ float    g_part[2][3 * NPIX];

// ---------------- helpers ----------------
__device__ __forceinline__ uint32_t pack_h2(float lo, float hi) {
    __half2 h = __floats2half2_rn(lo, hi);
    return *reinterpret_cast<uint32_t*>(&h);
}
__device__ __forceinline__ uint32_t hmul2u(uint32_t a, uint32_t b) {
    uint32_t d;
    asm("mul.f16x2 %0, %1, %2;" : "=r"(d) : "r"(a), "r"(b));
    return d;
}
__device__ __forceinline__ float fast_sin(float x) {
    const float INV_PI = 0.3183098861837907f;
    const float PI_HI  = 3.14159274101257324f;
    const float PI_LO  = -8.742277657347586e-8f;
    int   iq = __float2int_rn(x * INV_PI);
    float fq = (float)iq;
    float r  = fmaf(fq, -PI_HI, x);
    r        = fmaf(fq, -PI_LO, r);
    float r2 = r * r;
    float p  = fmaf(r2, 2.7183114939898219e-6f, -1.9839334836096632e-4f);
    p        = fmaf(r2, p, 8.3333293858894632e-3f);
    p        = fmaf(r2, p, -1.6666666641626524e-1f);
    p        = fmaf(r2 * r, p, r);
    return (iq & 1) ? -p : p;
}

#define MMA_F16(d, a, b0, b1) \
    asm volatile("mma.sync.aligned.m16n8k16.row.col.f32.f16.f16.f32 " \
        "{%0,%1,%2,%3}, {%4,%5,%6,%7}, {%8,%9}, {%0,%1,%2,%3};" \
        : "+f"((d)[0]), "+f"((d)[1]), "+f"((d)[2]), "+f"((d)[3]) \
        : "r"((a)[0]), "r"((a)[1]), "r"((a)[2]), "r"((a)[3]), \
          "r"(b0), "r"(b1))

// ---------------------------------------------------------------------------
// branch networks: 1024 threads/block, k-split partials + smem combine,
// final stage writes interleaved half2 layout directly (no f32 globals).
// ---------------------------------------------------------------------------
#define BR_SMEM_FLOATS (4096 + 4096 + 16384)   // s0, s1, sp
__global__ __launch_bounds__(1024)
void branch_kernel(const float* __restrict__ x, const float* __restrict__ y,
                   const float* __restrict__ Wbx, const float* __restrict__ bbx,
                   const float* __restrict__ Wby, const float* __restrict__ bby,
                   const float* __restrict__ Wp1, const float* __restrict__ bp1,
                   const float* __restrict__ Wp2, const float* __restrict__ bp2)
{
    extern __shared__ float sm[];
    float* s0 = sm;            // [16][256]
    float* s1 = sm + 4096;     // [16][256]
    float* sp = sm + 8192;     // partials

    const int tid = threadIdx.x;
    const int t   = tid & 255;
    const int q   = tid >> 8;
    const int br  = blockIdx.y;
    const float* coord = br ? y   : x;
    const float* Wb    = br ? Wby : Wbx;
    const float* bb    = br ? bby : bbx;
    uint32_t*    outph = br ? g_hyh : g_hxh;
    const int r0 = blockIdx.x * 16;

    if (q == 0) {
        float wv = Wb[t], bv = bb[t];
        #pragma unroll
        for (int r = 0; r < 16; r++)
            s0[r * 256 + t] = fast_sin(fmaf(coord[r0 + r], wv, bv));
    }
    __syncthreads();

    // h1 partial over k in [64q, 64q+64)
    {
        float acc[16];
        #pragma unroll
        for (int r = 0; r < 16; r++) acc[r] = 0.0f;
        const float4* wrow = (const float4*)(Wp1 + (size_t)t * HID + 64 * q);
        #pragma unroll 4
        for (int k4 = 0; k4 < 16; k4++) {
            float4 w = wrow[k4];
            const int base = 64 * q + 4 * k4;
            #pragma unroll
            for (int r = 0; r < 16; r++) {
                float4 h = *(const float4*)&s0[r * 256 + base];
                acc[r] = fmaf(w.x, h.x, acc[r]); acc[r] = fmaf(w.y, h.y, acc[r]);
                acc[r] = fmaf(w.z, h.z, acc[r]); acc[r] = fmaf(w.w, h.w, acc[r]);
            }
        }
        #pragma unroll
        for (int r = 0; r < 16; r++) sp[(q * 16 + r) * 256 + t] = acc[r];
    }
    __syncthreads();
    if (q == 0) {
        float b = bp1[t];
        #pragma unroll
        for (int r = 0; r < 16; r++) {
            float v = b + sp[r * 256 + t] + sp[(16 + r) * 256 + t]
                        + sp[(32 + r) * 256 + t] + sp[(48 + r) * 256 + t];
            s1[r * 256 + t] = fast_sin(v);
        }
    }
    __syncthreads();

    // h2 partial: output n = tid&511 over k in [128kh, 128kh+128)
    {
        const int n  = tid & 511;
        const int kh = tid >> 9;
        float acc[16];
        #pragma unroll
        for (int r = 0; r < 16; r++) acc[r] = 0.0f;
        const float4* wrow = (const float4*)(Wp2 + (size_t)n * HID + 128 * kh);
        #pragma unroll 4
        for (int k4 = 0; k4 < 32; k4++) {
            float4 w = wrow[k4];
            const int base = 128 * kh + 4 * k4;
            #pragma unroll
            for (int r = 0; r < 16; r++) {
                float4 h = *(const float4*)&s1[r * 256 + base];
                acc[r] = fmaf(w.x, h.x, acc[r]); acc[r] = fmaf(w.y, h.y, acc[r]);
                acc[r] = fmaf(w.z, h.z, acc[r]); acc[r] = fmaf(w.w, h.w, acc[r]);
            }
        }
        __syncthreads();   // sp reuse: all h1 reads complete
        #pragma unroll
        for (int r = 0; r < 16; r++) sp[(kh * 16 + r) * 512 + n] = acc[r];
    }
    __syncthreads();
    // combine into s0 (f32 result rows)
    if (tid < 256) {
        float b0 = bp2[t], b1 = bp2[t + 256];
        #pragma unroll
        for (int r = 0; r < 16; r++) {
            float v0 = b0 + sp[r * 512 + t]       + sp[(16 + r) * 512 + t];
            float v1 = b1 + sp[r * 512 + t + 256] + sp[(16 + r) * 512 + t + 256];
            s0[r * 256 + t] = fast_sin(v0) + fast_sin(v1);
        }
    }
    __syncthreads();
    // pack interleaved half2 pairs: slot s = kt*4+qk -> { n0..n0+1, n0+8..n0+9 }
    {
        const int r = tid >> 6;
        const int s = tid & 63;
        const int n0 = (s >> 2) * 16 + (s & 3) * 2;
        const float* row = s0 + r * 256;
        uint2 val;
        val.x = pack_h2(row[n0],     row[n0 + 1]);
        val.y = pack_h2(row[n0 + 8], row[n0 + 9]);
        ((uint2*)outph)[(size_t)(r0 + r) * 64 + s] = val;
    }
}

// ---------------------------------------------------------------------------
// merge: persistent fp16 mma.sync m16n8k16 + tensor-core Wm2 fold.
// CTA tile M=256 (32i x 8j) x N=128 (half) x K=256. Warp owns one j, full N.
// ---------------------------------------------------------------------------
#define SMB_B    0         // 16384 u32 fp16 fragments = 65536 B
#define SMB_HX   65536     // 32 rows x 136 u32 = 17408 B
#define SMB_HY   82944     // 8 rows x 136 u32 = 4352 B
#define SMB_BM1  87296     // 128 f32
#define SMB_TOT  87808

#define HXP 136            // u32 pitch (== 8 mod 32: LDS.64 conflict-free)
#define N_ITILES 24
#define TILES    (N_ITILES * 96)   // 2304 per half
#define N_GROUPS 74

__global__ __launch_bounds__(256, 1)
void merge_kernel(const float* __restrict__ Wm1, const float* __restrict__ bm1,
                  const float* __restrict__ Wm2)
{
    extern __shared__ __align__(16) char smem[];
    uint32_t* sBh   = (uint32_t*)(smem + SMB_B);
    uint32_t* s_hx2 = (uint32_t*)(smem + SMB_HX);
    uint32_t* s_hy2 = (uint32_t*)(smem + SMB_HY);
    float*    s_b1  = (float*)(smem + SMB_BM1);

    const int tid  = threadIdx.x;
    const int wid  = tid >> 5;
    const int lane = tid & 31;
    const int qk   = lane & 3;
    const int qr   = lane >> 2;

    const int cta   = blockIdx.x;
    const int hlf   = cta & 1;
    const int group = cta >> 1;
    const int h0    = hlf * 128;

    // ---- one-time: B-half (Wm1) as fp16 mma fragments ----
    for (int idx = tid; idx < 128 * 64; idx += 256) {
        const int n  = idx >> 6;
        const int f4 = idx & 63;
        float4 v = *(const float4*)(Wm1 + (size_t)(h0 + n) * HID + f4 * 4);
        uint32_t h2a = pack_h2(v.x, v.y);
        uint32_t h2b = pack_h2(v.z, v.w);
        const int nt = n >> 3, qr_l = n & 7, pr = nt >> 1, sub = nt & 1;
        #pragma unroll
        for (int e = 0; e < 2; e++) {
            const int p  = 2 * f4 + e;
            const int kt = p >> 3, w8 = p & 7;
            const int slot = (((kt * 8 + pr) * 32 + qr_l * 4 + (w8 & 3)) * 4)
                             + sub * 2 + (w8 >> 2);
            sBh[slot] = e ? h2b : h2a;
        }
    }
    if (tid < 128) s_b1[tid] = bm1[h0 + tid];
    __syncthreads();

    // ---- per-thread Wm2 fold-B fragments (built once, 16 regs) ----
    // fold GEMM: A = sin(h) [16 m x 16 k(n_hid)], B = Wm2^T [16 k x 8 c]
    // B frag: b0 = half2 W[k=2qk,2qk+1][c=qr], b1 = k+8; zero for qr >= 3
    uint2 bf[8];
    #pragma unroll
    for (int kt2 = 0; kt2 < 8; kt2++) {
        if (qr < 3) {
            const float* wsrc = Wm2 + (size_t)qr * HID + h0 + kt2 * 16 + 2 * qk;
            bf[kt2].x = pack_h2(wsrc[0], wsrc[1]);
            bf[kt2].y = pack_h2(wsrc[8], wsrc[9]);
        } else {
            bf[kt2].x = 0u; bf[kt2].y = 0u;
        }
    }

    // ---- persistent tile loop ----
    for (int t = group; t < TILES; t += N_GROUPS) {
        const int i0 = (t % N_ITILES) * 32;
        const int j0 = (t / N_ITILES) * 8;

        __syncthreads();
        // stage hx (32 rows x 32 uint4) / hy (8 rows x 32 uint4) — FULL rows
        for (int idx = tid; idx < 1024; idx += 256) {
            const int r = idx >> 5, c = idx & 31;
            *(uint4*)(s_hx2 + r * HXP + c * 4) =
                ((const uint4*)(g_hxh + (size_t)(i0 + r) * 128))[c];
        }
        {
            const int r = tid >> 5, c = tid & 31;   // 256 thr = 8 rows x 32 uint4
            *(uint4*)(s_hy2 + r * HXP + c * 4) =
                ((const uint4*)(g_hyh + (size_t)(j0 + r) * 128))[c];
        }
        __syncthreads();

        // accumulators initialized with bm1 (MMA accumulates on top)
        float d[2][16][4];
        #pragma unroll
        for (int nt = 0; nt < 16; nt++) {
            const float b0 = s_b1[nt * 8 + qk * 2 + 0];
            const float b1 = s_b1[nt * 8 + qk * 2 + 1];
            #pragma unroll
            for (int ih = 0; ih < 2; ih++) {
                d[ih][nt][0] = b0; d[ih][nt][1] = b1;
                d[ih][nt][2] = b0; d[ih][nt][3] = b1;
            }
        }

        const uint32_t* hxb = s_hx2 + qr * HXP;
        const uint32_t* hyb = s_hy2 + wid * HXP;

        #pragma unroll 2
        for (int kt = 0; kt < 16; kt++) {
            const int so = (kt * 4 + qk) * 2;
            const uint2 yu = *(const uint2*)(hyb + so);
            uint2 xu[4];
            #pragma unroll
            for (int u = 0; u < 4; u++)
                xu[u] = *(const uint2*)(hxb + u * 8 * HXP + so);
            uint32_t a[2][4];
            #pragma unroll
            for (int ih = 0; ih < 2; ih++) {
                a[ih][0] = hmul2u(xu[2 * ih + 0].x, yu.x);
                a[ih][1] = hmul2u(xu[2 * ih + 1].x, yu.x);
                a[ih][2] = hmul2u(xu[2 * ih + 0].y, yu.y);
                a[ih][3] = hmul2u(xu[2 * ih + 1].y, yu.y);
            }
            const uint4* bp4 = (const uint4*)sBh + (size_t)(kt * 8) * 32 + lane;
            #pragma unroll
            for (int p = 0; p < 8; p++) {
                uint4 B2 = bp4[p * 32];
                MMA_F16(d[0][2 * p],     a[0], B2.x, B2.y);
                MMA_F16(d[1][2 * p],     a[1], B2.x, B2.y);
                MMA_F16(d[0][2 * p + 1], a[0], B2.z, B2.w);
                MMA_F16(d[1][2 * p + 1], a[1], B2.z, B2.w);
            }
        }

        // ---- epilogue: sin -> pack -> fold via MMA (B = Wm2 frags) ----
        const int j = j0 + wid;
        float* bp = g_part[hlf];
        #pragma unroll
        for (int ih = 0; ih < 2; ih++) {
            float fd[4] = {0.f, 0.f, 0.f, 0.f};
            #pragma unroll
            for (int kt2 = 0; kt2 < 8; kt2++) {
                uint32_t a[4];
                a[0] = pack_h2(__sinf(d[ih][2 * kt2][0]),     __sinf(d[ih][2 * kt2][1]));
                a[1] = pack_h2(__sinf(d[ih][2 * kt2][2]),     __sinf(d[ih][2 * kt2][3]));
                a[2] = pack_h2(__sinf(d[ih][2 * kt2 + 1][0]), __sinf(d[ih][2 * kt2 + 1][1]));
                a[3] = pack_h2(__sinf(d[ih][2 * kt2 + 1][2]), __sinf(d[ih][2 * kt2 + 1][3]));
                MMA_F16(fd, a, bf[kt2].x, bf[kt2].y);
            }
            // D cols = c: qk==0 -> c0,c1 ; qk==1 -> c2 ; rows qr, qr+8
            const int il = i0 + 16 * ih + qr;
            const size_t pix = (size_t)j * HH + il;
            if (qk == 0) {
                bp[pix]            = fd[0];
                bp[pix + 8]        = fd[2];
                bp[NPIX + pix]     = fd[1];
                bp[NPIX + pix + 8] = fd[3];
            } else if (qk == 1) {
                bp[2 * NPIX + pix]     = fd[0];
                bp[2 * NPIX + pix + 8] = fd[2];
            }
        }
    }
}

// ---------------------------------------------------------------------------
__global__ __launch_bounds__(256)
void final_kernel(const float* __restrict__ bm2, float* __restrict__ out)
{
    const int idx = blockIdx.x * 256 + threadIdx.x;   // float4 index
    if (idx < 3 * NPIX / 4) {
        const int c = idx / (NPIX / 4);
        const float bc = bm2[c];
        float4 a = ((const float4*)g_part[0])[idx];
        float4 b = ((const float4*)g_part[1])[idx];
        float4 o;
        o.x = __fdividef(1.0f, 1.0f + __expf(-(a.x + b.x + bc)));
        o.y = __fdividef(1.0f, 1.0f + __expf(-(a.y + b.y + bc)));
        o.z = __fdividef(1.0f, 1.0f + __expf(-(a.z + b.z + bc)));
        o.w = __fdividef(1.0f, 1.0f + __expf(-(a.w + b.w + bc)));
        ((float4*)out)[idx] = o;
    }
}

// ---------------------------------------------------------------------------
extern "C" void kernel_launch(void* const* d_in, const int* in_sizes, int n_in,
                              void* d_out, int out_size) {
    const float* x   = (const float*)d_in[0];
    const float* y   = (const float*)d_in[1];
    const float* Wbx = (const float*)d_in[2];
    const float* bbx = (const float*)d_in[3];
    const float* Wby = (const float*)d_in[4];
    const float* bby = (const float*)d_in[5];
    const float* Wp1 = (const float*)d_in[6];
    const float* bp1 = (const float*)d_in[7];
    const float* Wp2 = (const float*)d_in[8];
    const float* bp2 = (const float*)d_in[9];
    const float* Wm1 = (const float*)d_in[10];
    const float* bm1 = (const float*)d_in[11];
    const float* Wm2 = (const float*)d_in[12];
    const float* bm2 = (const float*)d_in[13];
    float* out = (float*)d_out;

    cudaFuncSetAttribute(branch_kernel,
                         cudaFuncAttributeMaxDynamicSharedMemorySize,
                         BR_SMEM_FLOATS * 4);
    cudaFuncSetAttribute(merge_kernel,
                         cudaFuncAttributeMaxDynamicSharedMemorySize, SMB_TOT);

    branch_kernel<<<dim3(HH / 16, 2), 1024, BR_SMEM_FLOATS * 4>>>(
        x, y, Wbx, bbx, Wby, bby, Wp1, bp1, Wp2, bp2);
    merge_kernel<<<148, 256, SMB_TOT>>>(Wm1, bm1, Wm2);
    final_kernel<<<(3 * NPIX / 4 + 255) / 256, 256>>>(bm2, out);
}

// round 10
// speedup vs baseline: 1.0942x; 1.0722x over previous
#include <cuda_runtime.h>
#include <cuda_fp16.h>
#include <cstdint>

#define HH   768
#define WW   768
#define HID  256
#define NPIX (HH*WW)

// ---------------- scratch ----------------
// interleaved half2 layout per row: 64 uint2 slots; slot s=(kt*4+qk) holds
// half2 pairs { p = 8kt+qk, p+4 }  (p indexes n-pairs: n = 2p, 2p+1)
__device__ uint32_t g_hxh[HH * 128];
__device__ uint32_t g_hyh[WW * 128];
__device__ float    g_part[2][3 * NPIX];

// ---------------- helpers ----------------
__device__ __forceinline__ uint32_t pack_h2(float lo, float hi) {
    __half2 h = __floats2half2_rn(lo, hi);
    return *reinterpret_cast<uint32_t*>(&h);
}
__device__ __forceinline__ uint32_t hmul2u(uint32_t a, uint32_t b) {
    uint32_t d;
    asm("mul.f16x2 %0, %1, %2;" : "=r"(d) : "r"(a), "r"(b));
    return d;
}
__device__ __forceinline__ float fast_sin(float x) {
    const float INV_PI = 0.3183098861837907f;
    const float PI_HI  = 3.14159274101257324f;
    const float PI_LO  = -8.742277657347586e-8f;
    int   iq = __float2int_rn(x * INV_PI);
    float fq = (float)iq;
    float r  = fmaf(fq, -PI_HI, x);
    r        = fmaf(fq, -PI_LO, r);
    float r2 = r * r;
    float p  = fmaf(r2, 2.7183114939898219e-6f, -1.9839334836096632e-4f);
    p        = fmaf(r2, p, 8.3333293858894632e-3f);
    p        = fmaf(r2, p, -1.6666666641626524e-1f);
    p        = fmaf(r2 * r, p, r);
    return (iq & 1) ? -p : p;
}

#define MMA_F16(d, a, b0, b1) \
    asm volatile("mma.sync.aligned.m16n8k16.row.col.f32.f16.f16.f32 " \
        "{%0,%1,%2,%3}, {%4,%5,%6,%7}, {%8,%9}, {%0,%1,%2,%3};" \
        : "+f"((d)[0]), "+f"((d)[1]), "+f"((d)[2]), "+f"((d)[3]) \
        : "r"((a)[0]), "r"((a)[1]), "r"((a)[2]), "r"((a)[3]), \
          "r"(b0), "r"(b1))

// ---------------------------------------------------------------------------
// branch networks: 8 rows/block, 256 threads, 192 blocks total.
// Writes interleaved half2 layout directly.
// ---------------------------------------------------------------------------
__global__ __launch_bounds__(256)
void branch_kernel(const float* __restrict__ x, const float* __restrict__ y,
                   const float* __restrict__ Wbx, const float* __restrict__ bbx,
                   const float* __restrict__ Wby, const float* __restrict__ bby,
                   const float* __restrict__ Wp1, const float* __restrict__ bp1,
                   const float* __restrict__ Wp2, const float* __restrict__ bp2)
{
    __shared__ float s0[8 * 256];
    __shared__ float s1[8 * 256];

    const int t  = threadIdx.x;
    const int br = blockIdx.y;
    const float* coord = br ? y   : x;
    const float* Wb    = br ? Wby : Wbx;
    const float* bb    = br ? bby : bbx;
    uint32_t*    outph = br ? g_hyh : g_hxh;
    const int r0 = blockIdx.x * 8;

    {
        float wv = Wb[t], bv = bb[t];
        #pragma unroll
        for (int r = 0; r < 8; r++)
            s0[r * 256 + t] = fast_sin(fmaf(coord[r0 + r], wv, bv));
    }
    __syncthreads();

    // h1: thread t owns output column t for 8 rows
    {
        float acc[8]; float b = bp1[t];
        #pragma unroll
        for (int r = 0; r < 8; r++) acc[r] = b;
        const float4* wrow = (const float4*)(Wp1 + (size_t)t * HID);
        #pragma unroll 4
        for (int k4 = 0; k4 < 64; k4++) {
            float4 w = wrow[k4];
            #pragma unroll
            for (int r = 0; r < 8; r++) {
                float4 h = *(const float4*)&s0[r * 256 + k4 * 4];
                acc[r] = fmaf(w.x, h.x, acc[r]); acc[r] = fmaf(w.y, h.y, acc[r]);
                acc[r] = fmaf(w.z, h.z, acc[r]); acc[r] = fmaf(w.w, h.w, acc[r]);
            }
        }
        #pragma unroll
        for (int r = 0; r < 8; r++) s1[r * 256 + t] = fast_sin(acc[r]);
    }
    __syncthreads();

    // h2: thread t owns n=t and n=t+256; R-sum; result into s0
    {
        float acc0[8], acc1[8];
        float b0 = bp2[t], b1 = bp2[t + 256];
        #pragma unroll
        for (int r = 0; r < 8; r++) { acc0[r] = b0; acc1[r] = b1; }
        const float4* w0row = (const float4*)(Wp2 + (size_t)t * HID);
        const float4* w1row = (const float4*)(Wp2 + (size_t)(t + 256) * HID);
        #pragma unroll 4
        for (int k4 = 0; k4 < 64; k4++) {
            float4 w0 = w0row[k4], w1 = w1row[k4];
            #pragma unroll
            for (int r = 0; r < 8; r++) {
                float4 h = *(const float4*)&s1[r * 256 + k4 * 4];
                acc0[r] = fmaf(w0.x, h.x, acc0[r]); acc0[r] = fmaf(w0.y, h.y, acc0[r]);
                acc0[r] = fmaf(w0.z, h.z, acc0[r]); acc0[r] = fmaf(w0.w, h.w, acc0[r]);
                acc1[r] = fmaf(w1.x, h.x, acc1[r]); acc1[r] = fmaf(w1.y, h.y, acc1[r]);
                acc1[r] = fmaf(w1.z, h.z, acc1[r]); acc1[r] = fmaf(w1.w, h.w, acc1[r]);
            }
        }
        #pragma unroll
        for (int r = 0; r < 8; r++)
            s0[r * 256 + t] = fast_sin(acc0[r]) + fast_sin(acc1[r]);
    }
    __syncthreads();

    // pack interleaved half2 pairs: slot s = kt*4+qk -> { n0..n0+1, n0+8..n0+9 }
    {
        const int r = t >> 5;
        #pragma unroll
        for (int e = 0; e < 2; e++) {
            const int s = (t & 31) + 32 * e;
            const int n0 = (s >> 2) * 16 + (s & 3) * 2;
            const float* row = s0 + r * 256;
            uint2 val;
            val.x = pack_h2(row[n0],     row[n0 + 1]);
            val.y = pack_h2(row[n0 + 8], row[n0 + 9]);
            ((uint2*)outph)[(size_t)(r0 + r) * 64 + s] = val;
        }
    }
}

// ---------------------------------------------------------------------------
// merge: persistent fp16 mma.sync m16n8k16, 2 CTAs/SM.
// CTA tile M=128 (16i x 8j) x N=128 (half) x K=256. Warp owns one j, full N.
// ---------------------------------------------------------------------------
#define SMB_B    0         // 16384 u32 fp16 fragments = 65536 B
#define SMB_HX   65536     // 16 rows x 136 u32 = 8704 B
#define SMB_HY   74240     // 8 rows x 136 u32 = 4352 B
#define SMB_BM1  78592     // 128 f32 = 512 B
#define SMB_BF   79104     // fold-B frags [8 kt2][32 lane] uint2 = 2048 B
#define SMB_TOT  81152

#define HXP 136            // u32 pitch (== 8 mod 32: LDS.64 conflict-free)
#define N_ITILES 48        // 768/16
#define INSTANCES (2 * N_ITILES * 96)   // (half, tile) pairs = 9216
#define N_CTAS   296

__global__ __launch_bounds__(256, 2)
void merge_kernel(const float* __restrict__ Wm1, const float* __restrict__ bm1,
                  const float* __restrict__ Wm2)
{
    extern __shared__ __align__(16) char smem[];
    uint32_t* sBh   = (uint32_t*)(smem + SMB_B);
    uint32_t* s_hx2 = (uint32_t*)(smem + SMB_HX);
    uint32_t* s_hy2 = (uint32_t*)(smem + SMB_HY);
    float*    s_b1  = (float*)(smem + SMB_BM1);
    uint2*    s_bf  = (uint2*)(smem + SMB_BF);

    const int tid  = threadIdx.x;
    const int wid  = tid >> 5;
    const int lane = tid & 31;
    const int qk   = lane & 3;
    const int qr   = lane >> 2;

    const int cta = blockIdx.x;
    const int hlf = cta & 1;           // parity-fixed: B half stays resident
    const int h0  = hlf * 128;

    // ---- one-time: B-half (Wm1) as fp16 mma fragments ----
    for (int idx = tid; idx < 128 * 64; idx += 256) {
        const int n  = idx >> 6;
        const int f4 = idx & 63;
        float4 v = *(const float4*)(Wm1 + (size_t)(h0 + n) * HID + f4 * 4);
        uint32_t h2a = pack_h2(v.x, v.y);
        uint32_t h2b = pack_h2(v.z, v.w);
        const int nt = n >> 3, qr_l = n & 7, pr = nt >> 1, sub = nt & 1;
        #pragma unroll
        for (int e = 0; e < 2; e++) {
            const int p  = 2 * f4 + e;
            const int kt = p >> 3, w8 = p & 7;
            const int slot = (((kt * 8 + pr) * 32 + qr_l * 4 + (w8 & 3)) * 4)
                             + sub * 2 + (w8 >> 2);
            sBh[slot] = e ? h2b : h2a;
        }
    }
    if (tid < 128) s_b1[tid] = bm1[h0 + tid];
    // fold-B fragments into smem: [kt2][lane] (zero for c=qr>=3)
    {
        const int kt2 = tid >> 5, ln = tid & 31;
        const int fqk = ln & 3, fqr = ln >> 2;
        uint2 v = make_uint2(0u, 0u);
        if (fqr < 3) {
            const float* wsrc = Wm2 + (size_t)fqr * HID + h0 + kt2 * 16 + 2 * fqk;
            v.x = pack_h2(wsrc[0], wsrc[1]);
            v.y = pack_h2(wsrc[8], wsrc[9]);
        }
        s_bf[kt2 * 32 + ln] = v;
    }
    __syncthreads();

    // ---- persistent instance loop ----
    for (int inst = cta; inst < INSTANCES; inst += N_CTAS) {
        const int t  = inst >> 1;           // parity matches cta parity = hlf
        const int i0 = (t % N_ITILES) * 16;
        const int j0 = (t / N_ITILES) * 8;

        __syncthreads();
        // stage hx (16 rows x 32 uint4) / hy (8 rows x 32 uint4)
        for (int idx = tid; idx < 512; idx += 256) {
            const int r = idx >> 5, c = idx & 31;
            *(uint4*)(s_hx2 + r * HXP + c * 4) =
                ((const uint4*)(g_hxh + (size_t)(i0 + r) * 128))[c];
        }
        {
            const int r = tid >> 5, c = tid & 31;
            *(uint4*)(s_hy2 + r * HXP + c * 4) =
                ((const uint4*)(g_hyh + (size_t)(j0 + r) * 128))[c];
        }
        __syncthreads();

        // accumulators initialized with bm1 (MMA accumulates on top)
        float d[16][4];
        #pragma unroll
        for (int nt = 0; nt < 16; nt++) {
            const float b0 = s_b1[nt * 8 + qk * 2 + 0];
            const float b1 = s_b1[nt * 8 + qk * 2 + 1];
            d[nt][0] = b0; d[nt][1] = b1;
            d[nt][2] = b0; d[nt][3] = b1;
        }

        const uint32_t* hxb = s_hx2 + qr * HXP;
        const uint32_t* hyb = s_hy2 + wid * HXP;

        #pragma unroll 2
        for (int kt = 0; kt < 16; kt++) {
            const int so = (kt * 4 + qk) * 2;
            const uint2 yu = *(const uint2*)(hyb + so);
            const uint2 x0 = *(const uint2*)(hxb + so);
            const uint2 x1 = *(const uint2*)(hxb + 8 * HXP + so);
            uint32_t a[4];
            a[0] = hmul2u(x0.x, yu.x);
            a[1] = hmul2u(x1.x, yu.x);
            a[2] = hmul2u(x0.y, yu.y);
            a[3] = hmul2u(x1.y, yu.y);
            const uint4* bp4 = (const uint4*)sBh + (size_t)(kt * 8) * 32 + lane;
            #pragma unroll
            for (int p = 0; p < 8; p++) {
                uint4 B2 = bp4[p * 32];
                MMA_F16(d[2 * p],     a, B2.x, B2.y);
                MMA_F16(d[2 * p + 1], a, B2.z, B2.w);
            }
        }

        // ---- epilogue: sin -> pack -> fold via MMA (B = Wm2 frags) ----
        const int j = j0 + wid;
        float* bp = g_part[hlf];
        {
            float fd[4] = {0.f, 0.f, 0.f, 0.f};
            #pragma unroll
            for (int kt2 = 0; kt2 < 8; kt2++) {
                uint32_t a[4];
                a[0] = pack_h2(__sinf(d[2 * kt2][0]),     __sinf(d[2 * kt2][1]));
                a[1] = pack_h2(__sinf(d[2 * kt2][2]),     __sinf(d[2 * kt2][3]));
                a[2] = pack_h2(__sinf(d[2 * kt2 + 1][0]), __sinf(d[2 * kt2 + 1][1]));
                a[3] = pack_h2(__sinf(d[2 * kt2 + 1][2]), __sinf(d[2 * kt2 + 1][3]));
                uint2 bf = s_bf[kt2 * 32 + lane];
                MMA_F16(fd, a, bf.x, bf.y);
            }
            // D cols = c: qk==0 -> c0,c1 ; qk==1 -> c2 ; rows qr, qr+8
            const int il = i0 + qr;
            const size_t pix = (size_t)j * HH + il;
            if (qk == 0) {
                bp[pix]            = fd[0];
                bp[pix + 8]        = fd[2];
                bp[NPIX + pix]     = fd[1];
                bp[NPIX + pix + 8] = fd[3];
            } else if (qk == 1) {
                bp[2 * NPIX + pix]     = fd[0];
                bp[2 * NPIX + pix + 8] = fd[2];
            }
        }
    }
}

// ---------------------------------------------------------------------------
__global__ __launch_bounds__(256)
void final_kernel(const float* __restrict__ bm2, float* __restrict__ out)
{
    const int idx = blockIdx.x * 256 + threadIdx.x;   // float4 index
    if (idx < 3 * NPIX / 4) {
        const int c = idx / (NPIX / 4);
        const float bc = bm2[c];
        float4 a = ((const float4*)g_part[0])[idx];
        float4 b = ((const float4*)g_part[1])[idx];
        float4 o;
        o.x = __fdividef(1.0f, 1.0f + __expf(-(a.x + b.x + bc)));
        o.y = __fdividef(1.0f, 1.0f + __expf(-(a.y + b.y + bc)));
        o.z = __fdividef(1.0f, 1.0f + __expf(-(a.z + b.z + bc)));
        o.w = __fdividef(1.0f, 1.0f + __expf(-(a.w + b.w + bc)));
        ((float4*)out)[idx] = o;
    }
}

// ---------------------------------------------------------------------------
extern "C" void kernel_launch(void* const* d_in, const int* in_sizes, int n_in,
                              void* d_out, int out_size) {
    const float* x   = (const float*)d_in[0];
    const float* y   = (const float*)d_in[1];
    const float* Wbx = (const float*)d_in[2];
    const float* bbx = (const float*)d_in[3];
    const float* Wby = (const float*)d_in[4];
    const float* bby = (const float*)d_in[5];
    const float* Wp1 = (const float*)d_in[6];
    const float* bp1 = (const float*)d_in[7];
    const float* Wp2 = (const float*)d_in[8];
    const float* bp2 = (const float*)d_in[9];
    const float* Wm1 = (const float*)d_in[10];
    const float* bm1 = (const float*)d_in[11];
    const float* Wm2 = (const float*)d_in[12];
    const float* bm2 = (const float*)d_in[13];
    float* out = (float*)d_out;

    cudaFuncSetAttribute(merge_kernel,
                         cudaFuncAttributeMaxDynamicSharedMemorySize, SMB_TOT);

    branch_kernel<<<dim3(HH / 8, 2), 256>>>(x, y, Wbx, bbx, Wby, bby,
                                            Wp1, bp1, Wp2, bp2);
    merge_kernel<<<N_CTAS, 256, SMB_TOT>>>(Wm1, bm1, Wm2);
    final_kernel<<<(3 * NPIX / 4 + 255) / 256, 256>>>(bm2, out);
}

// round 11
// speedup vs baseline: 1.1177x; 1.0215x over previous
#include <cuda_runtime.h>
#include <cuda_fp16.h>
#include <cstdint>

#define HH   768
#define WW   768
#define HID  256
#define NPIX (HH*WW)

// ---------------- scratch ----------------
// interleaved half2 layout per row: 64 uint2 slots; slot s=(kt*4+qk) holds
// half2 pairs { p = 8kt+qk, p+4 }  (p indexes n-pairs: n = 2p, 2p+1)
__device__ uint32_t g_hxh[HH * 128];
__device__ uint32_t g_hyh[WW * 128];
__device__ float    g_part[2][3 * NPIX];

// ---------------- helpers ----------------
__device__ __forceinline__ uint32_t pack_h2(float lo, float hi) {
    __half2 h = __floats2half2_rn(lo, hi);
    return *reinterpret_cast<uint32_t*>(&h);
}
__device__ __forceinline__ uint32_t hmul2u(uint32_t a, uint32_t b) {
    uint32_t d;
    asm("mul.f16x2 %0, %1, %2;" : "=r"(d) : "r"(a), "r"(b));
    return d;
}
__device__ __forceinline__ float fast_sin(float x) {
    const float INV_PI = 0.3183098861837907f;
    const float PI_HI  = 3.14159274101257324f;
    const float PI_LO  = -8.742277657347586e-8f;
    int   iq = __float2int_rn(x * INV_PI);
    float fq = (float)iq;
    float r  = fmaf(fq, -PI_HI, x);
    r        = fmaf(fq, -PI_LO, r);
    float r2 = r * r;
    float p  = fmaf(r2, 2.7183114939898219e-6f, -1.9839334836096632e-4f);
    p        = fmaf(r2, p, 8.3333293858894632e-3f);
    p        = fmaf(r2, p, -1.6666666641626524e-1f);
    p        = fmaf(r2 * r, p, r);
    return (iq & 1) ? -p : p;
}

#define MMA_F16(d, a, b0, b1) \
    asm volatile("mma.sync.aligned.m16n8k16.row.col.f32.f16.f16.f32 " \
        "{%0,%1,%2,%3}, {%4,%5,%6,%7}, {%8,%9}, {%0,%1,%2,%3};" \
        : "+f"((d)[0]), "+f"((d)[1]), "+f"((d)[2]), "+f"((d)[3]) \
        : "r"((a)[0]), "r"((a)[1]), "r"((a)[2]), "r"((a)[3]), \
          "r"(b0), "r"(b1))

// ---------------------------------------------------------------------------
// branch networks: 512 threads, 12 rows/block, grid (64, 2).
// h1: thread = (col, row-half): 6 accs. h2: thread = one of 512 cols: 12 accs.
// R-sum via smem sin staging (overlaid on dead s0/s1).
// ---------------------------------------------------------------------------
__global__ __launch_bounds__(512)
void branch_kernel(const float* __restrict__ x, const float* __restrict__ y,
                   const float* __restrict__ Wbx, const float* __restrict__ bbx,
                   const float* __restrict__ Wby, const float* __restrict__ bby,
                   const float* __restrict__ Wp1, const float* __restrict__ bp1,
                   const float* __restrict__ Wp2, const float* __restrict__ bp2)
{
    __shared__ float sm[12 * 512];           // 24KB
    float* s0 = sm;                          // [12][256]
    float* s1 = sm + 12 * 256;               // [12][256]
    float* sp = sm;                          // overlay: [12][512] (s0,s1 dead)

    const int tid = threadIdx.x;
    const int col = tid & 255;
    const int rh  = tid >> 8;                // row-half 0/1
    const int br  = blockIdx.y;
    const float* coord = br ? y   : x;
    const float* Wb    = br ? Wby : Wbx;
    const float* bb    = br ? bby : bbx;
    uint32_t*    outph = br ? g_hyh : g_hxh;
    const int r0 = blockIdx.x * 12;

    // h0: rows rh*6..+5, column col
    {
        float wv = Wb[col], bv = bb[col];
        #pragma unroll
        for (int r2 = 0; r2 < 6; r2++) {
            const int r = rh * 6 + r2;
            s0[r * 256 + col] = fast_sin(fmaf(coord[r0 + r], wv, bv));
        }
    }
    __syncthreads();

    // h1: 6 accs over full K=256
    {
        float acc[6];
        float b = bp1[col];
        #pragma unroll
        for (int r2 = 0; r2 < 6; r2++) acc[r2] = b;
        const float4* wrow = (const float4*)(Wp1 + (size_t)col * HID);
        #pragma unroll 4
        for (int k4 = 0; k4 < 64; k4++) {
            float4 w = wrow[k4];
            #pragma unroll
            for (int r2 = 0; r2 < 6; r2++) {
                float4 h = *(const float4*)&s0[(rh * 6 + r2) * 256 + k4 * 4];
                acc[r2] = fmaf(w.x, h.x, acc[r2]); acc[r2] = fmaf(w.y, h.y, acc[r2]);
                acc[r2] = fmaf(w.z, h.z, acc[r2]); acc[r2] = fmaf(w.w, h.w, acc[r2]);
            }
        }
        __syncthreads();   // all s0 reads complete before s1 writes? (s1 disjoint; sync for s1 readiness below)
        #pragma unroll
        for (int r2 = 0; r2 < 6; r2++)
            s1[(rh * 6 + r2) * 256 + col] = fast_sin(acc[r2]);
    }
    __syncthreads();

    // h2: thread owns col n = tid (0..511), 12 rows
    float acc2[12];
    {
        float b = bp2[tid];
        #pragma unroll
        for (int r = 0; r < 12; r++) acc2[r] = b;
        const float4* wrow = (const float4*)(Wp2 + (size_t)tid * HID);
        #pragma unroll 4
        for (int k4 = 0; k4 < 64; k4++) {
            float4 w = wrow[k4];
            #pragma unroll
            for (int r = 0; r < 12; r++) {
                float4 h = *(const float4*)&s1[r * 256 + k4 * 4];
                acc2[r] = fmaf(w.x, h.x, acc2[r]); acc2[r] = fmaf(w.y, h.y, acc2[r]);
                acc2[r] = fmaf(w.z, h.z, acc2[r]); acc2[r] = fmaf(w.w, h.w, acc2[r]);
            }
        }
    }
    __syncthreads();   // s1 reads done -> sp overlay safe
    #pragma unroll
    for (int r = 0; r < 12; r++) sp[r * 512 + tid] = fast_sin(acc2[r]);
    __syncthreads();

    // pack interleaved half2 pairs: slot s = kt*4+qk -> { n0..n0+1, n0+8..n0+9 }
    for (int idx = tid; idx < 12 * 64; idx += 512) {
        const int r = idx >> 6, s = idx & 63;
        const int n0 = (s >> 2) * 16 + (s & 3) * 2;
        const float* row = sp + r * 512;
        uint2 val;
        val.x = pack_h2(row[n0]     + row[n0 + 256], row[n0 + 1] + row[n0 + 257]);
        val.y = pack_h2(row[n0 + 8] + row[n0 + 264], row[n0 + 9] + row[n0 + 265]);
        ((uint2*)outph)[(size_t)(r0 + r) * 64 + s] = val;
    }
}

// ---------------------------------------------------------------------------
// merge: persistent fp16 mma.sync m16n8k16, 2 CTAs/SM, B-reuse x4.
// CTA tile M=128 (16i x 8j) x N=128 (half) x K=256.
// 8 warps = 2 jw x 4 nw; warp = 4 j x N=32 (B held in regs across 4 j).
// Pixel partials combined across nw via smem buffer (race-free).
// ---------------------------------------------------------------------------
#define SMB_B    0         // 16384 u32 fp16 fragments = 65536 B
#define SMB_HX   65536     // 16 rows x 136 u32 = 8704 B
#define SMB_HY   74240     // 8 rows x 136 u32 = 4352 B
#define SMB_BM1  78592     // 128 f32 = 512 B
#define SMB_BF   79104     // fold-B frags [8 kt2][32 lane] uint2 = 2048 B
#define SMB_PART 81152     // [4 nw][384] f32 = 6144 B
#define SMB_TOT  87296

#define HXP 136            // u32 pitch
#define N_ITILES 48        // 768/16
#define INSTANCES (2 * N_ITILES * 96)   // 9216
#define N_CTAS   296

__global__ __launch_bounds__(256, 2)
void merge_kernel(const float* __restrict__ Wm1, const float* __restrict__ bm1,
                  const float* __restrict__ Wm2)
{
    extern __shared__ __align__(16) char smem[];
    uint32_t* sBh   = (uint32_t*)(smem + SMB_B);
    uint32_t* s_hx2 = (uint32_t*)(smem + SMB_HX);
    uint32_t* s_hy2 = (uint32_t*)(smem + SMB_HY);
    float*    s_b1  = (float*)(smem + SMB_BM1);
    uint2*    s_bf  = (uint2*)(smem + SMB_BF);
    float*    s_pt  = (float*)(smem + SMB_PART);

    const int tid  = threadIdx.x;
    const int wid  = tid >> 5;
    const int lane = tid & 31;
    const int qk   = lane & 3;
    const int qr   = lane >> 2;
    const int nw   = wid & 3;          // n-quarter
    const int jw   = wid >> 2;         // j-half

    const int cta = blockIdx.x;
    const int hlf = cta & 1;
    const int h0  = hlf * 128;

    // ---- one-time: B-half (Wm1) as fp16 mma fragments (paired layout) ----
    for (int idx = tid; idx < 128 * 64; idx += 256) {
        const int n  = idx >> 6;
        const int f4 = idx & 63;
        float4 v = *(const float4*)(Wm1 + (size_t)(h0 + n) * HID + f4 * 4);
        uint32_t h2a = pack_h2(v.x, v.y);
        uint32_t h2b = pack_h2(v.z, v.w);
        const int nt = n >> 3, qr_l = n & 7, pr = nt >> 1, sub = nt & 1;
        #pragma unroll
        for (int e = 0; e < 2; e++) {
            const int p  = 2 * f4 + e;
            const int kt = p >> 3, w8 = p & 7;
            const int slot = (((kt * 8 + pr) * 32 + qr_l * 4 + (w8 & 3)) * 4)
                             + sub * 2 + (w8 >> 2);
            sBh[slot] = e ? h2b : h2a;
        }
    }
    if (tid < 128) s_b1[tid] = bm1[h0 + tid];
    // fold-B fragments: [kt2][lane] (zero for c=fqr>=3)
    {
        const int kt2 = tid >> 5, ln = tid & 31;
        const int fqk = ln & 3, fqr = ln >> 2;
        uint2 v = make_uint2(0u, 0u);
        if (fqr < 3) {
            const float* wsrc = Wm2 + (size_t)fqr * HID + h0 + kt2 * 16 + 2 * fqk;
            v.x = pack_h2(wsrc[0], wsrc[1]);
            v.y = pack_h2(wsrc[8], wsrc[9]);
        }
        s_bf[kt2 * 32 + ln] = v;
    }
    __syncthreads();

    // ---- persistent instance loop ----
    for (int inst = cta; inst < INSTANCES; inst += N_CTAS) {
        const int t  = inst >> 1;           // parity matches cta parity = hlf
        const int i0 = (t % N_ITILES) * 16;
        const int j0 = (t / N_ITILES) * 8;

        __syncthreads();
        // stage hx (16 rows x 32 uint4) / hy (8 rows x 32 uint4)
        for (int idx = tid; idx < 512; idx += 256) {
            const int r = idx >> 5, c = idx & 31;
            *(uint4*)(s_hx2 + r * HXP + c * 4) =
                ((const uint4*)(g_hxh + (size_t)(i0 + r) * 128))[c];
        }
        {
            const int r = tid >> 5, c = tid & 31;
            *(uint4*)(s_hy2 + r * HXP + c * 4) =
                ((const uint4*)(g_hyh + (size_t)(j0 + r) * 128))[c];
        }
        __syncthreads();

        // accumulators initialized with bm1 (MMA accumulates on top)
        float d[4][4][4];    // [jj][local nt][frag]; global nt = 4*nw + local
        #pragma unroll
        for (int ntl = 0; ntl < 4; ntl++) {
            const float b0 = s_b1[(4 * nw + ntl) * 8 + qk * 2 + 0];
            const float b1 = s_b1[(4 * nw + ntl) * 8 + qk * 2 + 1];
            #pragma unroll
            for (int jj = 0; jj < 4; jj++) {
                d[jj][ntl][0] = b0; d[jj][ntl][1] = b1;
                d[jj][ntl][2] = b0; d[jj][ntl][3] = b1;
            }
        }

        const uint32_t* hxb = s_hx2 + qr * HXP;
        const uint32_t* hyb = s_hy2 + (jw * 4) * HXP;
        const uint4*    bb  = (const uint4*)sBh + lane;

        #pragma unroll 2
        for (int kt = 0; kt < 16; kt++) {
            const int so = (kt * 4 + qk) * 2;
            const uint2 x0 = *(const uint2*)(hxb + so);
            const uint2 x1 = *(const uint2*)(hxb + 8 * HXP + so);
            const uint4 Ba = bb[(kt * 8 + 2 * nw) * 32];
            const uint4 Bb = bb[(kt * 8 + 2 * nw + 1) * 32];
            #pragma unroll
            for (int jj = 0; jj < 4; jj++) {
                const uint2 yu = *(const uint2*)(hyb + jj * HXP + so);
                uint32_t a[4];
                a[0] = hmul2u(x0.x, yu.x);
                a[1] = hmul2u(x1.x, yu.x);
                a[2] = hmul2u(x0.y, yu.y);
                a[3] = hmul2u(x1.y, yu.y);
                MMA_F16(d[jj][0], a, Ba.x, Ba.y);
                MMA_F16(d[jj][1], a, Ba.z, Ba.w);
                MMA_F16(d[jj][2], a, Bb.x, Bb.y);
                MMA_F16(d[jj][3], a, Bb.z, Bb.w);
            }
        }

        // ---- epilogue: sin -> pack -> fold-MMA over warp's N=32 ----
        float* pp = s_pt + nw * 384;
        #pragma unroll
        for (int jj = 0; jj < 4; jj++) {
            float fd[4] = {0.f, 0.f, 0.f, 0.f};
            #pragma unroll
            for (int e = 0; e < 2; e++) {
                const int kt2 = 2 * nw + e;      // global n-chunk of 16
                uint32_t a[4];
                a[0] = pack_h2(__sinf(d[jj][2 * e][0]),     __sinf(d[jj][2 * e][1]));
                a[1] = pack_h2(__sinf(d[jj][2 * e][2]),     __sinf(d[jj][2 * e][3]));
                a[2] = pack_h2(__sinf(d[jj][2 * e + 1][0]), __sinf(d[jj][2 * e + 1][1]));
                a[3] = pack_h2(__sinf(d[jj][2 * e + 1][2]), __sinf(d[jj][2 * e + 1][3]));
                uint2 bf = s_bf[kt2 * 32 + lane];
                MMA_F16(fd, a, bf.x, bf.y);
            }
            const int jl = jw * 4 + jj;
            // D cols: qk==0 -> c0,c1 ; qk==1 -> c2 ; rows qr, qr+8
            if (qk == 0) {
                pp[(jl * 16 + qr) * 3 + 0]     = fd[0];
                pp[(jl * 16 + qr) * 3 + 1]     = fd[1];
                pp[(jl * 16 + qr + 8) * 3 + 0] = fd[2];
                pp[(jl * 16 + qr + 8) * 3 + 1] = fd[3];
            } else if (qk == 1) {
                pp[(jl * 16 + qr) * 3 + 2]     = fd[0];
                pp[(jl * 16 + qr + 8) * 3 + 2] = fd[2];
            }
        }
        __syncthreads();

        // combine 4 nw partials -> g_part
        for (int idx = tid; idx < 384; idx += 256) {
            float v = s_pt[idx] + s_pt[384 + idx] + s_pt[768 + idx] + s_pt[1152 + idx];
            const int c   = idx % 3;
            const int rem = idx / 3;
            const int i   = rem & 15;
            const int j   = rem >> 4;
            g_part[hlf][(size_t)c * NPIX + (size_t)(j0 + j) * HH + (i0 + i)] = v;
        }
    }
}

// ---------------------------------------------------------------------------
__global__ __launch_bounds__(256)
void final_kernel(const float* __restrict__ bm2, float* __restrict__ out)
{
    const int idx = blockIdx.x * 256 + threadIdx.x;   // float4 index
    if (idx < 3 * NPIX / 4) {
        const int c = idx / (NPIX / 4);
        const float bc = bm2[c];
        float4 a = ((const float4*)g_part[0])[idx];
        float4 b = ((const float4*)g_part[1])[idx];
        float4 o;
        o.x = __fdividef(1.0f, 1.0f + __expf(-(a.x + b.x + bc)));
        o.y = __fdividef(1.0f, 1.0f + __expf(-(a.y + b.y + bc)));
        o.z = __fdividef(1.0f, 1.0f + __expf(-(a.z + b.z + bc)));
        o.w = __fdividef(1.0f, 1.0f + __expf(-(a.w + b.w + bc)));
        ((float4*)out)[idx] = o;
    }
}

// ---------------------------------------------------------------------------
extern "C" void kernel_launch(void* const* d_in, const int* in_sizes, int n_in,
                              void* d_out, int out_size) {
    const float* x   = (const float*)d_in[0];
    const float* y   = (const float*)d_in[1];
    const float* Wbx = (const float*)d_in[2];
    const float* bbx = (const float*)d_in[3];
    const float* Wby = (const float*)d_in[4];
    const float* bby = (const float*)d_in[5];
    const float* Wp1 = (const float*)d_in[6];
    const float* bp1 = (const float*)d_in[7];
    const float* Wp2 = (const float*)d_in[8];
    const float* bp2 = (const float*)d_in[9];
    const float* Wm1 = (const float*)d_in[10];
    const float* bm1 = (const float*)d_in[11];
    const float* Wm2 = (const float*)d_in[12];
    const float* bm2 = (const float*)d_in[13];
    float* out = (float*)d_out;

    cudaFuncSetAttribute(merge_kernel,
                         cudaFuncAttributeMaxDynamicSharedMemorySize, SMB_TOT);

    branch_kernel<<<dim3(HH / 12, 2), 512>>>(x, y, Wbx, bbx, Wby, bby,
                                             Wp1, bp1, Wp2, bp2);
    merge_kernel<<<N_CTAS, 256, SMB_TOT>>>(Wm1, bm1, Wm2);
    final_kernel<<<(3 * NPIX / 4 + 255) / 256, 256>>>(bm2, out);
}

// round 12
// speedup vs baseline: 1.2425x; 1.1117x over previous
#include <cuda_runtime.h>
#include <cuda_fp16.h>
#include <cstdint>

#define HH   768
#define WW   768
#define HID  256
#define NPIX (HH*WW)

// ---------------- scratch ----------------
// interleaved half2 layout per row: 64 uint2 slots; slot s=(kt*4+qk) holds
// half2 pairs { p = 8kt+qk, p+4 }  (p indexes n-pairs: n = 2p, 2p+1)
__device__ uint32_t g_hxh[HH * 128];
__device__ uint32_t g_hyh[WW * 128];
__device__ float    g_part[2][3 * NPIX];

// ---------------- helpers ----------------
__device__ __forceinline__ uint32_t pack_h2(float lo, float hi) {
    __half2 h = __floats2half2_rn(lo, hi);
    return *reinterpret_cast<uint32_t*>(&h);
}
__device__ __forceinline__ uint32_t hmul2u(uint32_t a, uint32_t b) {
    uint32_t d;
    asm("mul.f16x2 %0, %1, %2;" : "=r"(d) : "r"(a), "r"(b));
    return d;
}
__device__ __forceinline__ float fast_sin(float x) {
    const float INV_PI = 0.3183098861837907f;
    const float PI_HI  = 3.14159274101257324f;
    const float PI_LO  = -8.742277657347586e-8f;
    int   iq = __float2int_rn(x * INV_PI);
    float fq = (float)iq;
    float r  = fmaf(fq, -PI_HI, x);
    r        = fmaf(fq, -PI_LO, r);
    float r2 = r * r;
    float p  = fmaf(r2, 2.7183114939898219e-6f, -1.9839334836096632e-4f);
    p        = fmaf(r2, p, 8.3333293858894632e-3f);
    p        = fmaf(r2, p, -1.6666666641626524e-1f);
    p        = fmaf(r2 * r, p, r);
    return (iq & 1) ? -p : p;
}

#define MMA_F16(d, a, b0, b1) \
    asm volatile("mma.sync.aligned.m16n8k16.row.col.f32.f16.f16.f32 " \
        "{%0,%1,%2,%3}, {%4,%5,%6,%7}, {%8,%9}, {%0,%1,%2,%3};" \
        : "+f"((d)[0]), "+f"((d)[1]), "+f"((d)[2]), "+f"((d)[3]) \
        : "r"((a)[0]), "r"((a)[1]), "r"((a)[2]), "r"((a)[3]), \
          "r"(b0), "r"(b1))

// ---------------------------------------------------------------------------
// branch networks: 12 rows/block, 256 threads, grid (64, 2) = 128 blocks.
// R1-style: h1 thread owns col t (12 accs); h2 thread owns cols t, t+256.
// ---------------------------------------------------------------------------
__global__ __launch_bounds__(256)
void branch_kernel(const float* __restrict__ x, const float* __restrict__ y,
                   const float* __restrict__ Wbx, const float* __restrict__ bbx,
                   const float* __restrict__ Wby, const float* __restrict__ bby,
                   const float* __restrict__ Wp1, const float* __restrict__ bp1,
                   const float* __restrict__ Wp2, const float* __restrict__ bp2)
{
    __shared__ float s0[12 * 256];
    __shared__ float s1[12 * 256];

    const int t  = threadIdx.x;
    const int br = blockIdx.y;
    const float* coord = br ? y   : x;
    const float* Wb    = br ? Wby : Wbx;
    const float* bb    = br ? bby : bbx;
    uint32_t*    outph = br ? g_hyh : g_hxh;
    const int r0 = blockIdx.x * 12;

    {
        float wv = Wb[t], bv = bb[t];
        #pragma unroll
        for (int r = 0; r < 12; r++)
            s0[r * 256 + t] = fast_sin(fmaf(coord[r0 + r], wv, bv));
    }
    __syncthreads();

    // h1: thread t owns output column t for 12 rows
    {
        float acc[12]; float b = bp1[t];
        #pragma unroll
        for (int r = 0; r < 12; r++) acc[r] = b;
        const float4* wrow = (const float4*)(Wp1 + (size_t)t * HID);
        #pragma unroll 4
        for (int k4 = 0; k4 < 64; k4++) {
            float4 w = wrow[k4];
            #pragma unroll
            for (int r = 0; r < 12; r++) {
                float4 h = *(const float4*)&s0[r * 256 + k4 * 4];
                acc[r] = fmaf(w.x, h.x, acc[r]); acc[r] = fmaf(w.y, h.y, acc[r]);
                acc[r] = fmaf(w.z, h.z, acc[r]); acc[r] = fmaf(w.w, h.w, acc[r]);
            }
        }
        #pragma unroll
        for (int r = 0; r < 12; r++) s1[r * 256 + t] = fast_sin(acc[r]);
    }
    __syncthreads();

    // h2: thread t owns n=t and n=t+256; R-sum; result -> s0 (dead after h1)
    {
        float acc0[12], acc1[12];
        float b0 = bp2[t], b1 = bp2[t + 256];
        #pragma unroll
        for (int r = 0; r < 12; r++) { acc0[r] = b0; acc1[r] = b1; }
        const float4* w0row = (const float4*)(Wp2 + (size_t)t * HID);
        const float4* w1row = (const float4*)(Wp2 + (size_t)(t + 256) * HID);
        #pragma unroll 4
        for (int k4 = 0; k4 < 64; k4++) {
            float4 w0 = w0row[k4], w1 = w1row[k4];
            #pragma unroll
            for (int r = 0; r < 12; r++) {
                float4 h = *(const float4*)&s1[r * 256 + k4 * 4];
                acc0[r] = fmaf(w0.x, h.x, acc0[r]); acc0[r] = fmaf(w0.y, h.y, acc0[r]);
                acc0[r] = fmaf(w0.z, h.z, acc0[r]); acc0[r] = fmaf(w0.w, h.w, acc0[r]);
                acc1[r] = fmaf(w1.x, h.x, acc1[r]); acc1[r] = fmaf(w1.y, h.y, acc1[r]);
                acc1[r] = fmaf(w1.z, h.z, acc1[r]); acc1[r] = fmaf(w1.w, h.w, acc1[r]);
            }
        }
        #pragma unroll
        for (int r = 0; r < 12; r++)
            s0[r * 256 + t] = fast_sin(acc0[r]) + fast_sin(acc1[r]);
    }
    __syncthreads();

    // pack interleaved half2 pairs: slot s = kt*4+qk -> { n0..n0+1, n0+8..n0+9 }
    for (int idx = t; idx < 12 * 64; idx += 256) {
        const int r = idx >> 6, s = idx & 63;
        const int n0 = (s >> 2) * 16 + (s & 3) * 2;
        const float* row = s0 + r * 256;
        uint2 val;
        val.x = pack_h2(row[n0],     row[n0 + 1]);
        val.y = pack_h2(row[n0 + 8], row[n0 + 9]);
        ((uint2*)outph)[(size_t)(r0 + r) * 64 + s] = val;
    }
}

// ---------------------------------------------------------------------------
// merge: persistent fp16 mma.sync m16n8k16, 2 CTAs/SM, B-reuse x4,
// software-pipelined: double-buffered hx/hy stages + partial buffer,
// register prefetch of next instance, ONE __syncthreads per instance.
// ---------------------------------------------------------------------------
#define SMB_B    0          // 65536 B
#define SMB_HX0  65536      // 8704 B
#define SMB_HY0  74240      // 4352 B
#define SMB_HX1  78592      // 8704 B
#define SMB_HY1  87296      // 4352 B
#define SMB_BM1  91648      // 512 B
#define SMB_BF   92160      // 2048 B
#define SMB_PT0  94208      // 6144 B
#define SMB_PT1  100352     // 6144 B
#define SMB_TOT  106496

#define HXP 136             // u32 pitch
#define N_ITILES 48
#define INSTANCES (2 * N_ITILES * 96)   // 9216
#define N_CTAS   296

__global__ __launch_bounds__(256, 2)
void merge_kernel(const float* __restrict__ Wm1, const float* __restrict__ bm1,
                  const float* __restrict__ Wm2)
{
    extern __shared__ __align__(16) char smem[];
    uint32_t* sBh  = (uint32_t*)(smem + SMB_B);
    float*    s_b1 = (float*)(smem + SMB_BM1);
    uint2*    s_bf = (uint2*)(smem + SMB_BF);

    const int tid  = threadIdx.x;
    const int wid  = tid >> 5;
    const int lane = tid & 31;
    const int qk   = lane & 3;
    const int qr   = lane >> 2;
    const int nw   = wid & 3;
    const int jw   = wid >> 2;

    const int cta = blockIdx.x;
    const int hlf = cta & 1;
    const int h0  = hlf * 128;

    // ---- one-time: B-half (Wm1) as fp16 mma fragments (paired layout) ----
    for (int idx = tid; idx < 128 * 64; idx += 256) {
        const int n  = idx >> 6;
        const int f4 = idx & 63;
        float4 v = *(const float4*)(Wm1 + (size_t)(h0 + n) * HID + f4 * 4);
        uint32_t h2a = pack_h2(v.x, v.y);
        uint32_t h2b = pack_h2(v.z, v.w);
        const int nt = n >> 3, qr_l = n & 7, pr = nt >> 1, sub = nt & 1;
        #pragma unroll
        for (int e = 0; e < 2; e++) {
            const int p  = 2 * f4 + e;
            const int kt = p >> 3, w8 = p & 7;
            const int slot = (((kt * 8 + pr) * 32 + qr_l * 4 + (w8 & 3)) * 4)
                             + sub * 2 + (w8 >> 2);
            sBh[slot] = e ? h2b : h2a;
        }
    }
    if (tid < 128) s_b1[tid] = bm1[h0 + tid];
    {
        const int kt2 = tid >> 5, ln = tid & 31;
        const int fqk = ln & 3, fqr = ln >> 2;
        uint2 v = make_uint2(0u, 0u);
        if (fqr < 3) {
            const float* wsrc = Wm2 + (size_t)fqr * HID + h0 + kt2 * 16 + 2 * fqk;
            v.x = pack_h2(wsrc[0], wsrc[1]);
            v.y = pack_h2(wsrc[8], wsrc[9]);
        }
        s_bf[kt2 * 32 + ln] = v;
    }

    // ---- prologue: stage instance `cta` into buffer 0 ----
    const int rx = tid >> 5, cx = tid & 31;   // staging coords
    {
        const int t0 = cta >> 1;
        const int i0 = (t0 % N_ITILES) * 16;
        const int j0 = (t0 / N_ITILES) * 8;
        uint32_t* dx = (uint32_t*)(smem + SMB_HX0);
        uint32_t* dy = (uint32_t*)(smem + SMB_HY0);
        *(uint4*)(dx + rx * HXP + cx * 4) =
            ((const uint4*)g_hxh)[(size_t)(i0 + rx) * 32 + cx];
        *(uint4*)(dx + (rx + 8) * HXP + cx * 4) =
            ((const uint4*)g_hxh)[(size_t)(i0 + rx + 8) * 32 + cx];
        *(uint4*)(dy + rx * HXP + cx * 4) =
            ((const uint4*)g_hyh)[(size_t)(j0 + rx) * 32 + cx];
    }
    __syncthreads();

    int stage = 0, pbuf = 0;

    // ---- persistent instance loop: ONE sync per instance ----
    for (int inst = cta; inst < INSTANCES; inst += N_CTAS) {
        const int t  = inst >> 1;
        const int i0 = (t % N_ITILES) * 16;
        const int j0 = (t / N_ITILES) * 8;

        // prefetch next instance into registers (overlaps MMA loop)
        const bool hasNext = (inst + N_CTAS) < INSTANCES;
        uint4 phx0, phx1, phy;
        if (hasNext) {
            const int t2  = (inst + N_CTAS) >> 1;
            const int i0n = (t2 % N_ITILES) * 16;
            const int j0n = (t2 / N_ITILES) * 8;
            phx0 = ((const uint4*)g_hxh)[(size_t)(i0n + rx) * 32 + cx];
            phx1 = ((const uint4*)g_hxh)[(size_t)(i0n + rx + 8) * 32 + cx];
            phy  = ((const uint4*)g_hyh)[(size_t)(j0n + rx) * 32 + cx];
        }

        uint32_t* s_hx2 = (uint32_t*)(smem + (stage ? SMB_HX1 : SMB_HX0));
        uint32_t* s_hy2 = (uint32_t*)(smem + (stage ? SMB_HY1 : SMB_HY0));

        // accumulators initialized with bm1 (MMA accumulates on top)
        float d[4][4][4];    // [jj][local nt][frag]; global nt = 4*nw + local
        #pragma unroll
        for (int ntl = 0; ntl < 4; ntl++) {
            const float b0 = s_b1[(4 * nw + ntl) * 8 + qk * 2 + 0];
            const float b1 = s_b1[(4 * nw + ntl) * 8 + qk * 2 + 1];
            #pragma unroll
            for (int jj = 0; jj < 4; jj++) {
                d[jj][ntl][0] = b0; d[jj][ntl][1] = b1;
                d[jj][ntl][2] = b0; d[jj][ntl][3] = b1;
            }
        }

        const uint32_t* hxb = s_hx2 + qr * HXP;
        const uint32_t* hyb = s_hy2 + (jw * 4) * HXP;
        const uint4*    bb  = (const uint4*)sBh + lane;

        #pragma unroll 2
        for (int kt = 0; kt < 16; kt++) {
            const int so = (kt * 4 + qk) * 2;
            const uint2 x0 = *(const uint2*)(hxb + so);
            const uint2 x1 = *(const uint2*)(hxb + 8 * HXP + so);
            const uint4 Ba = bb[(kt * 8 + 2 * nw) * 32];
            const uint4 Bb = bb[(kt * 8 + 2 * nw + 1) * 32];
            #pragma unroll
            for (int jj = 0; jj < 4; jj++) {
                const uint2 yu = *(const uint2*)(hyb + jj * HXP + so);
                uint32_t a[4];
                a[0] = hmul2u(x0.x, yu.x);
                a[1] = hmul2u(x1.x, yu.x);
                a[2] = hmul2u(x0.y, yu.y);
                a[3] = hmul2u(x1.y, yu.y);
                MMA_F16(d[jj][0], a, Ba.x, Ba.y);
                MMA_F16(d[jj][1], a, Ba.z, Ba.w);
                MMA_F16(d[jj][2], a, Bb.x, Bb.y);
                MMA_F16(d[jj][3], a, Bb.z, Bb.w);
            }
        }

        // store prefetched tiles into the other stage (no sync needed yet)
        if (hasNext) {
            uint32_t* dx = (uint32_t*)(smem + (stage ? SMB_HX0 : SMB_HX1));
            uint32_t* dy = (uint32_t*)(smem + (stage ? SMB_HY0 : SMB_HY1));
            *(uint4*)(dx + rx * HXP + cx * 4)       = phx0;
            *(uint4*)(dx + (rx + 8) * HXP + cx * 4) = phx1;
            *(uint4*)(dy + rx * HXP + cx * 4)       = phy;
        }

        // ---- epilogue: sin -> pack -> fold-MMA over warp's N=32 ----
        float* s_pt = (float*)(smem + (pbuf ? SMB_PT1 : SMB_PT0));
        float* pp = s_pt + nw * 384;
        #pragma unroll
        for (int jj = 0; jj < 4; jj++) {
            float fd[4] = {0.f, 0.f, 0.f, 0.f};
            #pragma unroll
            for (int e = 0; e < 2; e++) {
                const int kt2 = 2 * nw + e;
                uint32_t a[4];
                a[0] = pack_h2(__sinf(d[jj][2 * e][0]),     __sinf(d[jj][2 * e][1]));
                a[1] = pack_h2(__sinf(d[jj][2 * e][2]),     __sinf(d[jj][2 * e][3]));
                a[2] = pack_h2(__sinf(d[jj][2 * e + 1][0]), __sinf(d[jj][2 * e + 1][1]));
                a[3] = pack_h2(__sinf(d[jj][2 * e + 1][2]), __sinf(d[jj][2 * e + 1][3]));
                uint2 bf = s_bf[kt2 * 32 + lane];
                MMA_F16(fd, a, bf.x, bf.y);
            }
            const int jl = jw * 4 + jj;
            if (qk == 0) {
                pp[(jl * 16 + qr) * 3 + 0]     = fd[0];
                pp[(jl * 16 + qr) * 3 + 1]     = fd[1];
                pp[(jl * 16 + qr + 8) * 3 + 0] = fd[2];
                pp[(jl * 16 + qr + 8) * 3 + 1] = fd[3];
            } else if (qk == 1) {
                pp[(jl * 16 + qr) * 3 + 2]     = fd[0];
                pp[(jl * 16 + qr + 8) * 3 + 2] = fd[2];
            }
        }
        __syncthreads();   // s_pt[pbuf] ready + next stage ready

        // combine 4 nw partials -> g_part
        for (int idx = tid; idx < 384; idx += 256) {
            float v = s_pt[idx] + s_pt[384 + idx] + s_pt[768 + idx] + s_pt[1152 + idx];
            const int c   = idx % 3;
            const int rem = idx / 3;
            const int i   = rem & 15;
            const int j   = rem >> 4;
            g_part[hlf][(size_t)c * NPIX + (size_t)(j0 + j) * HH + (i0 + i)] = v;
        }

        stage ^= 1; pbuf ^= 1;
    }
}

// ---------------------------------------------------------------------------
__global__ __launch_bounds__(256)
void final_kernel(const float* __restrict__ bm2, float* __restrict__ out)
{
    const int idx = blockIdx.x * 256 + threadIdx.x;   // float4 index
    if (idx < 3 * NPIX / 4) {
        const int c = idx / (NPIX / 4);
        const float bc = bm2[c];
        float4 a = ((const float4*)g_part[0])[idx];
        float4 b = ((const float4*)g_part[1])[idx];
        float4 o;
        o.x = __fdividef(1.0f, 1.0f + __expf(-(a.x + b.x + bc)));
        o.y = __fdividef(1.0f, 1.0f + __expf(-(a.y + b.y + bc)));
        o.z = __fdividef(1.0f, 1.0f + __expf(-(a.z + b.z + bc)));
        o.w = __fdividef(1.0f, 1.0f + __expf(-(a.w + b.w + bc)));
        ((float4*)out)[idx] = o;
    }
}

// ---------------------------------------------------------------------------
extern "C" void kernel_launch(void* const* d_in, const int* in_sizes, int n_in,
                              void* d_out, int out_size) {
    const float* x   = (const float*)d_in[0];
    const float* y   = (const float*)d_in[1];
    const float* Wbx = (const float*)d_in[2];
    const float* bbx = (const float*)d_in[3];
    const float* Wby = (const float*)d_in[4];
    const float* bby = (const float*)d_in[5];
    const float* Wp1 = (const float*)d_in[6];
    const float* bp1 = (const float*)d_in[7];
    const float* Wp2 = (const float*)d_in[8];
    const float* bp2 = (const float*)d_in[9];
    const float* Wm1 = (const float*)d_in[10];
    const float* bm1 = (const float*)d_in[11];
    const float* Wm2 = (const float*)d_in[12];
    const float* bm2 = (const float*)d_in[13];
    float* out = (float*)d_out;

    cudaFuncSetAttribute(merge_kernel,
                         cudaFuncAttributeMaxDynamicSharedMemorySize, SMB_TOT);

    branch_kernel<<<dim3(HH / 12, 2), 256>>>(x, y, Wbx, bbx, Wby, bby,
                                             Wp1, bp1, Wp2, bp2);
    merge_kernel<<<N_CTAS, 256, SMB_TOT>>>(Wm1, bm1, Wm2);
    final_kernel<<<(3 * NPIX / 4 + 255) / 256, 256>>>(bm2, out);
}

// round 13
// speedup vs baseline: 1.2524x; 1.0080x over previous
#include <cuda_runtime.h>
#include <cuda_fp16.h>
#include <cstdint>

#define HH   768
#define WW   768
#define HID  256
#define NPIX (HH*WW)

// ---------------- scratch ----------------
__device__ uint32_t g_hxh[HH * 128];
__device__ uint32_t g_hyh[WW * 128];

// ---------------- helpers ----------------
__device__ __forceinline__ uint32_t pack_h2(float lo, float hi) {
    __half2 h = __floats2half2_rn(lo, hi);
    return *reinterpret_cast<uint32_t*>(&h);
}
__device__ __forceinline__ uint32_t hmul2u(uint32_t a, uint32_t b) {
    uint32_t d;
    asm("mul.f16x2 %0, %1, %2;" : "=r"(d) : "r"(a), "r"(b));
    return d;
}
__device__ __forceinline__ float fast_sin(float x) {
    const float INV_PI = 0.3183098861837907f;
    const float PI_HI  = 3.14159274101257324f;
    const float PI_LO  = -8.742277657347586e-8f;
    int   iq = __float2int_rn(x * INV_PI);
    float fq = (float)iq;
    float r  = fmaf(fq, -PI_HI, x);
    r        = fmaf(fq, -PI_LO, r);
    float r2 = r * r;
    float p  = fmaf(r2, 2.7183114939898219e-6f, -1.9839334836096632e-4f);
    p        = fmaf(r2, p, 8.3333293858894632e-3f);
    p        = fmaf(r2, p, -1.6666666641626524e-1f);
    p        = fmaf(r2 * r, p, r);
    return (iq & 1) ? -p : p;
}

#define MMA_F16(d, a, b0, b1) \
    asm volatile("mma.sync.aligned.m16n8k16.row.col.f32.f16.f16.f32 " \
        "{%0,%1,%2,%3}, {%4,%5,%6,%7}, {%8,%9}, {%0,%1,%2,%3};" \
        : "+f"((d)[0]), "+f"((d)[1]), "+f"((d)[2]), "+f"((d)[3]) \
        : "r"((a)[0]), "r"((a)[1]), "r"((a)[2]), "r"((a)[3]), \
          "r"(b0), "r"(b1))

// ---------------------------------------------------------------------------
// branch networks: 12 rows/block, 256 threads, grid (64, 2). unroll 8.
// ---------------------------------------------------------------------------
__global__ __launch_bounds__(256)
void branch_kernel(const float* __restrict__ x, const float* __restrict__ y,
                   const float* __restrict__ Wbx, const float* __restrict__ bbx,
                   const float* __restrict__ Wby, const float* __restrict__ bby,
                   const float* __restrict__ Wp1, const float* __restrict__ bp1,
                   const float* __restrict__ Wp2, const float* __restrict__ bp2)
{
    __shared__ float s0[12 * 256];
    __shared__ float s1[12 * 256];

    const int t  = threadIdx.x;
    const int br = blockIdx.y;
    const float* coord = br ? y   : x;
    const float* Wb    = br ? Wby : Wbx;
    const float* bb    = br ? bby : bbx;
    uint32_t*    outph = br ? g_hyh : g_hxh;
    const int r0 = blockIdx.x * 12;

    {
        float wv = Wb[t], bv = bb[t];
        #pragma unroll
        for (int r = 0; r < 12; r++)
            s0[r * 256 + t] = fast_sin(fmaf(coord[r0 + r], wv, bv));
    }
    __syncthreads();

    // h1: thread t owns output column t for 12 rows
    {
        float acc[12]; float b = bp1[t];
        #pragma unroll
        for (int r = 0; r < 12; r++) acc[r] = b;
        const float4* wrow = (const float4*)(Wp1 + (size_t)t * HID);
        #pragma unroll 8
        for (int k4 = 0; k4 < 64; k4++) {
            float4 w = wrow[k4];
            #pragma unroll
            for (int r = 0; r < 12; r++) {
                float4 h = *(const float4*)&s0[r * 256 + k4 * 4];
                acc[r] = fmaf(w.x, h.x, acc[r]); acc[r] = fmaf(w.y, h.y, acc[r]);
                acc[r] = fmaf(w.z, h.z, acc[r]); acc[r] = fmaf(w.w, h.w, acc[r]);
            }
        }
        #pragma unroll
        for (int r = 0; r < 12; r++) s1[r * 256 + t] = fast_sin(acc[r]);
    }
    __syncthreads();

    // h2: thread t owns n=t and n=t+256; R-sum; result -> s0
    {
        float acc0[12], acc1[12];
        float b0 = bp2[t], b1 = bp2[t + 256];
        #pragma unroll
        for (int r = 0; r < 12; r++) { acc0[r] = b0; acc1[r] = b1; }
        const float4* w0row = (const float4*)(Wp2 + (size_t)t * HID);
        const float4* w1row = (const float4*)(Wp2 + (size_t)(t + 256) * HID);
        #pragma unroll 8
        for (int k4 = 0; k4 < 64; k4++) {
            float4 w0 = w0row[k4], w1 = w1row[k4];
            #pragma unroll
            for (int r = 0; r < 12; r++) {
                float4 h = *(const float4*)&s1[r * 256 + k4 * 4];
                acc0[r] = fmaf(w0.x, h.x, acc0[r]); acc0[r] = fmaf(w0.y, h.y, acc0[r]);
                acc0[r] = fmaf(w0.z, h.z, acc0[r]); acc0[r] = fmaf(w0.w, h.w, acc0[r]);
                acc1[r] = fmaf(w1.x, h.x, acc1[r]); acc1[r] = fmaf(w1.y, h.y, acc1[r]);
                acc1[r] = fmaf(w1.z, h.z, acc1[r]); acc1[r] = fmaf(w1.w, h.w, acc1[r]);
            }
        }
        #pragma unroll
        for (int r = 0; r < 12; r++)
            s0[r * 256 + t] = fast_sin(acc0[r]) + fast_sin(acc1[r]);
    }
    __syncthreads();

    // pack interleaved half2 pairs
    for (int idx = t; idx < 12 * 64; idx += 256) {
        const int r = idx >> 6, s = idx & 63;
        const int n0 = (s >> 2) * 16 + (s & 3) * 2;
        const float* row = s0 + r * 256;
        uint2 val;
        val.x = pack_h2(row[n0],     row[n0 + 1]);
        val.y = pack_h2(row[n0 + 8], row[n0 + 9]);
        ((uint2*)outph)[(size_t)(r0 + r) * 64 + s] = val;
    }
}

// ---------------------------------------------------------------------------
// merge: persistent fp16 mma.sync m16n8k16, FULL N=256 per CTA, 512 threads
// (16 warps = 8 nw x 2 jw), 1 CTA/SM (4 warps/SMSP). Instance = 16i x 8j.
// Epilogue folds Wm2 via MMA, combines 8 nw partials, applies bm2+sigmoid,
// writes `out` directly (final_kernel eliminated).
// ---------------------------------------------------------------------------
#define SMB_B    0          // 32768 u32 = 131072 B
#define SMB_HX0  131072     // 16 x 136 u32 = 8704 B
#define SMB_HY0  139776     // 8 x 136 u32 = 4352 B
#define SMB_HX1  144128     // 8704 B
#define SMB_HY1  152832     // 4352 B
#define SMB_BM1  157184     // 256 f32 = 1024 B
#define SMB_BF   158208     // [16 kt2][32 lane] uint2 = 4096 B
#define SMB_PT0  162304     // [8 nw][384] f32 = 12288 B
#define SMB_PT1  174592     // 12288 B
#define SMB_TOT  186880

#define HXP 136             // u32 pitch
#define N_ITILES 48
#define INSTANCES (N_ITILES * 96)   // 4608
#define N_CTAS   148

__global__ __launch_bounds__(512, 1)
void merge_kernel(const float* __restrict__ Wm1, const float* __restrict__ bm1,
                  const float* __restrict__ Wm2, const float* __restrict__ bm2,
                  float* __restrict__ outg)
{
    extern __shared__ __align__(16) char smem[];
    uint32_t* sBh  = (uint32_t*)(smem + SMB_B);
    float*    s_b1 = (float*)(smem + SMB_BM1);
    uint2*    s_bf = (uint2*)(smem + SMB_BF);

    const int tid  = threadIdx.x;
    const int wid  = tid >> 5;
    const int lane = tid & 31;
    const int qk   = lane & 3;
    const int qr   = lane >> 2;
    const int nw   = wid & 7;          // n-eighth (N=32 each)
    const int jw   = wid >> 3;         // j-half (4 j each)

    const int cta = blockIdx.x;

    // ---- one-time: full B (Wm1, 256n x 256k) as fp16 mma fragments ----
    for (int idx = tid; idx < 256 * 64; idx += 512) {
        const int n  = idx >> 6;
        const int f4 = idx & 63;
        float4 v = *(const float4*)(Wm1 + (size_t)n * HID + f4 * 4);
        uint32_t h2a = pack_h2(v.x, v.y);
        uint32_t h2b = pack_h2(v.z, v.w);
        const int nt = n >> 3, qr_l = n & 7, pr = nt >> 1, sub = nt & 1;
        #pragma unroll
        for (int e = 0; e < 2; e++) {
            const int p  = 2 * f4 + e;
            const int kt = p >> 3, w8 = p & 7;
            const int slot = (((kt * 16 + pr) * 32 + qr_l * 4 + (w8 & 3)) * 4)
                             + sub * 2 + (w8 >> 2);
            sBh[slot] = e ? h2b : h2a;
        }
    }
    if (tid < 256) s_b1[tid] = bm1[tid];
    {   // fold-B fragments: [16 kt2][32 lane]
        const int kt2 = tid >> 5, ln = tid & 31;
        const int fqk = ln & 3, fqr = ln >> 2;
        uint2 v = make_uint2(0u, 0u);
        if (fqr < 3) {
            const float* wsrc = Wm2 + (size_t)fqr * HID + kt2 * 16 + 2 * fqk;
            v.x = pack_h2(wsrc[0], wsrc[1]);
            v.y = pack_h2(wsrc[8], wsrc[9]);
        }
        s_bf[kt2 * 32 + ln] = v;
    }

    // ---- prologue: stage instance `cta` into buffer 0 ----
    const int rx = tid >> 5, cx = tid & 31;          // hx: 16 rows x 32 uint4
    const int ry = (tid & 255) >> 5;                 // hy: 8 rows x 32 uint4 (tid<256)
    {
        const int t0 = cta;
        const int i0 = (t0 % N_ITILES) * 16;
        const int j0 = (t0 / N_ITILES) * 8;
        uint32_t* dx = (uint32_t*)(smem + SMB_HX0);
        uint32_t* dy = (uint32_t*)(smem + SMB_HY0);
        *(uint4*)(dx + rx * HXP + cx * 4) =
            ((const uint4*)g_hxh)[(size_t)(i0 + rx) * 32 + cx];
        if (tid < 256)
            *(uint4*)(dy + ry * HXP + cx * 4) =
                ((const uint4*)g_hyh)[(size_t)(j0 + ry) * 32 + cx];
    }
    __syncthreads();

    int stage = 0, pbuf = 0;

    // ---- persistent instance loop: ONE sync per instance ----
    for (int inst = cta; inst < INSTANCES; inst += N_CTAS) {
        const int i0 = (inst % N_ITILES) * 16;
        const int j0 = (inst / N_ITILES) * 8;

        // prefetch next instance into registers (overlaps MMA loop)
        const bool hasNext = (inst + N_CTAS) < INSTANCES;
        uint4 phx, phy;
        if (hasNext) {
            const int t2  = inst + N_CTAS;
            const int i0n = (t2 % N_ITILES) * 16;
            const int j0n = (t2 / N_ITILES) * 8;
            phx = ((const uint4*)g_hxh)[(size_t)(i0n + rx) * 32 + cx];
            if (tid < 256)
                phy = ((const uint4*)g_hyh)[(size_t)(j0n + ry) * 32 + cx];
        }

        uint32_t* s_hx2 = (uint32_t*)(smem + (stage ? SMB_HX1 : SMB_HX0));
        uint32_t* s_hy2 = (uint32_t*)(smem + (stage ? SMB_HY1 : SMB_HY0));

        // accumulators initialized with bm1 (MMA accumulates on top)
        float d[4][4][4];    // [jj][local nt][frag]; global nt = 4*nw + ntl
        #pragma unroll
        for (int ntl = 0; ntl < 4; ntl++) {
            const float b0 = s_b1[(4 * nw + ntl) * 8 + qk * 2 + 0];
            const float b1 = s_b1[(4 * nw + ntl) * 8 + qk * 2 + 1];
            #pragma unroll
            for (int jj = 0; jj < 4; jj++) {
                d[jj][ntl][0] = b0; d[jj][ntl][1] = b1;
                d[jj][ntl][2] = b0; d[jj][ntl][3] = b1;
            }
        }

        const uint32_t* hxb = s_hx2 + qr * HXP;
        const uint32_t* hyb = s_hy2 + (jw * 4) * HXP;
        const uint4*    bb  = (const uint4*)sBh + lane;

        #pragma unroll 2
        for (int kt = 0; kt < 16; kt++) {
            const int so = (kt * 4 + qk) * 2;
            const uint2 x0 = *(const uint2*)(hxb + so);
            const uint2 x1 = *(const uint2*)(hxb + 8 * HXP + so);
            const uint4 Ba = bb[(kt * 16 + 2 * nw) * 32];
            const uint4 Bb = bb[(kt * 16 + 2 * nw + 1) * 32];
            #pragma unroll
            for (int jj = 0; jj < 4; jj++) {
                const uint2 yu = *(const uint2*)(hyb + jj * HXP + so);
                uint32_t a[4];
                a[0] = hmul2u(x0.x, yu.x);
                a[1] = hmul2u(x1.x, yu.x);
                a[2] = hmul2u(x0.y, yu.y);
                a[3] = hmul2u(x1.y, yu.y);
                MMA_F16(d[jj][0], a, Ba.x, Ba.y);
                MMA_F16(d[jj][1], a, Ba.z, Ba.w);
                MMA_F16(d[jj][2], a, Bb.x, Bb.y);
                MMA_F16(d[jj][3], a, Bb.z, Bb.w);
            }
        }

        // store prefetched tiles into the other stage
        if (hasNext) {
            uint32_t* dx = (uint32_t*)(smem + (stage ? SMB_HX0 : SMB_HX1));
            uint32_t* dy = (uint32_t*)(smem + (stage ? SMB_HY0 : SMB_HY1));
            *(uint4*)(dx + rx * HXP + cx * 4) = phx;
            if (tid < 256)
                *(uint4*)(dy + ry * HXP + cx * 4) = phy;
        }

        // ---- epilogue: sin -> pack -> fold-MMA over warp's N=32 ----
        float* s_pt = (float*)(smem + (pbuf ? SMB_PT1 : SMB_PT0));
        float* pp = s_pt + nw * 384;
        #pragma unroll
        for (int jj = 0; jj < 4; jj++) {
            float fd[4] = {0.f, 0.f, 0.f, 0.f};
            #pragma unroll
            for (int e = 0; e < 2; e++) {
                const int kt2 = 2 * nw + e;
                uint32_t a[4];
                a[0] = pack_h2(__sinf(d[jj][2 * e][0]),     __sinf(d[jj][2 * e][1]));
                a[1] = pack_h2(__sinf(d[jj][2 * e][2]),     __sinf(d[jj][2 * e][3]));
                a[2] = pack_h2(__sinf(d[jj][2 * e + 1][0]), __sinf(d[jj][2 * e + 1][1]));
                a[3] = pack_h2(__sinf(d[jj][2 * e + 1][2]), __sinf(d[jj][2 * e + 1][3]));
                uint2 bf = s_bf[kt2 * 32 + lane];
                MMA_F16(fd, a, bf.x, bf.y);
            }
            const int jl = jw * 4 + jj;    // 0..7
            if (qk == 0) {
                pp[(jl * 16 + qr) * 3 + 0]     = fd[0];
                pp[(jl * 16 + qr) * 3 + 1]     = fd[1];
                pp[(jl * 16 + qr + 8) * 3 + 0] = fd[2];
                pp[(jl * 16 + qr + 8) * 3 + 1] = fd[3];
            } else if (qk == 1) {
                pp[(jl * 16 + qr) * 3 + 2]     = fd[0];
                pp[(jl * 16 + qr + 8) * 3 + 2] = fd[2];
            }
        }
        __syncthreads();   // s_pt[pbuf] ready + next stage ready

        // combine 8 nw partials + bm2 + sigmoid -> out (direct)
        if (tid < 384) {
            float v = 0.f;
            #pragma unroll
            for (int w = 0; w < 8; w++) v += s_pt[w * 384 + tid];
            const int c   = tid % 3;
            const int rem = tid / 3;
            const int i   = rem & 15;
            const int j   = rem >> 4;
            v += bm2[c];
            outg[(size_t)c * NPIX + (size_t)(j0 + j) * HH + (i0 + i)] =
                __fdividef(1.0f, 1.0f + __expf(-v));
        }

        stage ^= 1; pbuf ^= 1;
    }
}

// ---------------------------------------------------------------------------
extern "C" void kernel_launch(void* const* d_in, const int* in_sizes, int n_in,
                              void* d_out, int out_size) {
    const float* x   = (const float*)d_in[0];
    const float* y   = (const float*)d_in[1];
    const float* Wbx = (const float*)d_in[2];
    const float* bbx = (const float*)d_in[3];
    const float* Wby = (const float*)d_in[4];
    const float* bby = (const float*)d_in[5];
    const float* Wp1 = (const float*)d_in[6];
    const float* bp1 = (const float*)d_in[7];
    const float* Wp2 = (const float*)d_in[8];
    const float* bp2 = (const float*)d_in[9];
    const float* Wm1 = (const float*)d_in[10];
    const float* bm1 = (const float*)d_in[11];
    const float* Wm2 = (const float*)d_in[12];
    const float* bm2 = (const float*)d_in[13];
    float* out = (float*)d_out;

    cudaFuncSetAttribute(merge_kernel,
                         cudaFuncAttributeMaxDynamicSharedMemorySize, SMB_TOT);

    branch_kernel<<<dim3(HH / 12, 2), 256>>>(x, y, Wbx, bbx, Wby, bby,
                                             Wp1, bp1, Wp2, bp2);
    merge_kernel<<<N_CTAS, 512, SMB_TOT>>>(Wm1, bm1, Wm2, bm2, out);
}